// round 5
// baseline (speedup 1.0000x reference)
#include <cuda_runtime.h>

typedef unsigned long long u64;

// ---------------- f32x2 packed-math helpers (sm_103a) ----------------
__device__ __forceinline__ u64 fma2(u64 a, u64 b, u64 c) {
    u64 d;
    asm("fma.rn.f32x2 %0, %1, %2, %3;" : "=l"(d) : "l"(a), "l"(b), "l"(c));
    return d;
}
__device__ __forceinline__ u64 pack2(float lo, float hi) {
    u64 d;
    asm("mov.b64 %0, {%1, %2};" : "=l"(d) : "f"(lo), "f"(hi));
    return d;
}
__device__ __forceinline__ float2 unpack2(u64 v) {
    float2 r;
    asm("mov.b64 {%0, %1}, %2;" : "=f"(r.x), "=f"(r.y) : "l"(v));
    return r;
}

// Scratch
__device__ float g_qproj[4 * 256 * 1024];
__device__ float g_kproj[4 * 256 * 1024];
__device__ float g_vproj[4 * 256 * 1024];
__device__ float g_qT[8 * 1024 * 128];    // [ng][pix][c], scaled by 1/T
__device__ float g_kT[8 * 1024 * 128];
__device__ float g_vT[8 * 1024 * 128];
__device__ float g_VbT[2 * 225 * 128];    // [g][w][c]
__device__ float g_agg[1024 * 4 * 256];
__device__ float g_logits[8 * 225 * 1024]; // [ng][wpos][pix]

// ---------------------------------------------------------------------------
// Projection GEMM: Y[n,d,hw] = sum_c W[d,c] X[n,c,hw] + b[d]
// 128 threads, tile 64d x 128m, micro 8x8. grid (32 m, 4 d, 3 p).
// ---------------------------------------------------------------------------
__global__ void __launch_bounds__(128) proj_kernel(
        const float* __restrict__ q, const float* __restrict__ k,
        const float* __restrict__ v,
        const float* __restrict__ Wq, const float* __restrict__ bq,
        const float* __restrict__ Wk, const float* __restrict__ bk,
        const float* __restrict__ Wv, const float* __restrict__ bv) {
    __shared__ float w_s[32 * 68];    // [kk][d]
    __shared__ float x_s[32 * 128];   // [kk][m]

    const int p  = blockIdx.z;
    const int m0 = blockIdx.x * 128;
    const int d0 = blockIdx.y * 64;
    const int n  = m0 >> 10;
    const int hw0 = m0 & 1023;
    const int tid = threadIdx.x;

    const float *X, *Wm, *B;
    float* Y;
    if (p == 0)      { X = q; Wm = Wq; B = bq; Y = g_qproj; }
    else if (p == 1) { X = k; Wm = Wk; B = bk; Y = g_kproj; }
    else             { X = v; Wm = Wv; B = bv; Y = g_vproj; }

    const int td = tid >> 4;   // 0..7 -> d rows td*8..+7
    const int tm = tid & 15;   // m cols 2tm+32mq

    u64 acc[8][4];
    #pragma unroll
    for (int dd = 0; dd < 8; dd++) {
        float b = B[d0 + td * 8 + dd];
        u64 bb = pack2(b, b);
        #pragma unroll
        for (int mq = 0; mq < 4; mq++) acc[dd][mq] = bb;
    }

    const int dl   = tid >> 1;     // 0..63 (W row)
    const int half = tid & 1;      // k half

    for (int kb = 0; kb < 8; kb++) {
        const int k0 = kb * 32;
        {
            const float* src = Wm + (d0 + dl) * 256 + k0 + half * 16;
            #pragma unroll
            for (int qq = 0; qq < 4; qq++) {
                float4 f = *(const float4*)(src + qq * 4);
                int kk = half * 16 + qq * 4;
                w_s[(kk + 0) * 68 + dl] = f.x;
                w_s[(kk + 1) * 68 + dl] = f.y;
                w_s[(kk + 2) * 68 + dl] = f.z;
                w_s[(kk + 3) * 68 + dl] = f.w;
            }
        }
        #pragma unroll
        for (int r = 0; r < 8; r++) {
            int idx = tid + r * 128;         // 0..1023 float4 slots
            int kk = idx >> 5, m4 = idx & 31;
            *(float4*)(x_s + kk * 128 + m4 * 4) =
                *(const float4*)(X + (n * 256 + k0 + kk) * 1024 + hw0 + m4 * 4);
        }
        __syncthreads();

        #pragma unroll 8
        for (int kk = 0; kk < 32; kk++) {
            float4 wa = *(const float4*)(w_s + kk * 68 + td * 8);
            float4 wb = *(const float4*)(w_s + kk * 68 + td * 8 + 4);
            u64 xv[4];
            #pragma unroll
            for (int mq = 0; mq < 4; mq++)
                xv[mq] = *(const u64*)(x_s + kk * 128 + 2 * tm + 32 * mq);
            u64 wr[8];
            wr[0] = pack2(wa.x, wa.x); wr[1] = pack2(wa.y, wa.y);
            wr[2] = pack2(wa.z, wa.z); wr[3] = pack2(wa.w, wa.w);
            wr[4] = pack2(wb.x, wb.x); wr[5] = pack2(wb.y, wb.y);
            wr[6] = pack2(wb.z, wb.z); wr[7] = pack2(wb.w, wb.w);
            #pragma unroll
            for (int dd = 0; dd < 8; dd++)
                #pragma unroll
                for (int mq = 0; mq < 4; mq++)
                    acc[dd][mq] = fma2(wr[dd], xv[mq], acc[dd][mq]);
        }
        __syncthreads();
    }

    #pragma unroll
    for (int dd = 0; dd < 8; dd++) {
        float* yp = Y + (n * 256 + d0 + td * 8 + dd) * 1024 + hw0 + 2 * tm;
        #pragma unroll
        for (int mq = 0; mq < 4; mq++)
            *(float2*)(yp + 32 * mq) = unpack2(acc[dd][mq]);
    }
}

// ---------------------------------------------------------------------------
// Transpose kernel: [ng][c][pix] -> [ng][pix][c]; q scaled by 1/T.
// grid (32 pixtile, 4 ctile, 24 = src*8+ng), 256 threads.
// ---------------------------------------------------------------------------
__global__ void __launch_bounds__(256) transpose_kernel() {
    __shared__ float t[32][33];
    const int pix0 = blockIdx.x * 32;
    const int c0   = blockIdx.y * 32;
    const int z    = blockIdx.z;
    const int src  = z >> 3;
    const int ng   = z & 7;
    const int tid  = threadIdx.x;

    const float* in;
    float* out;
    float scale = 1.f;
    if (src == 0) { in = g_qproj; out = g_qT; scale = 0.08838834764831845f; }
    else if (src == 1) { in = g_kproj; out = g_kT; }
    else { in = g_vproj; out = g_vT; }
    in  += ng * 131072;
    out += ng * 131072;

    const int r = tid >> 5, j = tid & 31;
    #pragma unroll
    for (int kk = 0; kk < 4; kk++)
        t[r + 8 * kk][j] = in[(c0 + r + 8 * kk) * 1024 + pix0 + j];
    __syncthreads();
    #pragma unroll
    for (int kk = 0; kk < 4; kk++)
        out[(pix0 + r + 8 * kk) * 128 + c0 + j] = t[j][r + 8 * kk] * scale;
}

// ---------------------------------------------------------------------------
// VbT: [g][c][w] -> [g][w][c]
// ---------------------------------------------------------------------------
__global__ void __launch_bounds__(256) vbt_kernel(const float* __restrict__ Vb) {
    int i = blockIdx.x * 256 + threadIdx.x;
    if (i >= 28800) return;
    int g = blockIdx.y;
    int w = i >> 7, c = i & 127;
    g_VbT[g * 28800 + w * 128 + c] = Vb[g * 28800 + c * 225 + w];
}

// ---------------------------------------------------------------------------
// rel+mask GEMM: g_logits = valid ? Wrel.q + brel : -1e8
// ---------------------------------------------------------------------------
__global__ void __launch_bounds__(256) rel_kernel(
        const float* __restrict__ Wrel, const float* __restrict__ brel) {
    __shared__ float w_s[32 * 68];
    __shared__ float x_s[32 * 128];

    const int pix0 = blockIdx.x * 128;
    const int d0   = blockIdx.y * 64;
    const int ng   = blockIdx.z;
    const int g    = ng & 1;
    const int tid  = threadIdx.x;

    const float* Wg = Wrel + g * 225 * 128;
    const float* X  = g_qproj + ng * 128 * 1024;

    const int td = tid >> 4;
    const int tm = tid & 15;

    u64 acc[4][4];
    #pragma unroll
    for (int dd = 0; dd < 4; dd++)
        #pragma unroll
        for (int mq = 0; mq < 4; mq++) acc[dd][mq] = 0ull;

    const int ldq = tid >> 3;
    const int lc4 = tid & 7;
    const int lk  = tid >> 5;
    const int lm4 = tid & 31;

    for (int kb = 0; kb < 4; kb++) {
        const int k0 = kb * 32;
        {
            float4 z = make_float4(0.f, 0.f, 0.f, 0.f);
            float4 fa = (d0 + ldq < 225)
                ? *(const float4*)(Wg + (d0 + ldq) * 128 + k0 + lc4 * 4) : z;
            float4 fb = (d0 + ldq + 32 < 225)
                ? *(const float4*)(Wg + (d0 + ldq + 32) * 128 + k0 + lc4 * 4) : z;
            w_s[(lc4 * 4 + 0) * 68 + ldq] = fa.x;
            w_s[(lc4 * 4 + 1) * 68 + ldq] = fa.y;
            w_s[(lc4 * 4 + 2) * 68 + ldq] = fa.z;
            w_s[(lc4 * 4 + 3) * 68 + ldq] = fa.w;
            w_s[(lc4 * 4 + 0) * 68 + ldq + 32] = fb.x;
            w_s[(lc4 * 4 + 1) * 68 + ldq + 32] = fb.y;
            w_s[(lc4 * 4 + 2) * 68 + ldq + 32] = fb.z;
            w_s[(lc4 * 4 + 3) * 68 + ldq + 32] = fb.w;
        }
        #pragma unroll
        for (int r = 0; r < 4; r++) {
            *(float4*)(x_s + (lk + 8 * r) * 128 + lm4 * 4) =
                *(const float4*)(X + (k0 + lk + 8 * r) * 1024 + pix0 + lm4 * 4);
        }
        __syncthreads();

        #pragma unroll 8
        for (int kk = 0; kk < 32; kk++) {
            float4 wv = *(const float4*)(w_s + kk * 68 + td * 4);
            u64 xv[4];
            #pragma unroll
            for (int mq = 0; mq < 4; mq++)
                xv[mq] = *(const u64*)(x_s + kk * 128 + 2 * tm + 32 * mq);
            u64 w0 = pack2(wv.x, wv.x), w1 = pack2(wv.y, wv.y);
            u64 w2 = pack2(wv.z, wv.z), w3 = pack2(wv.w, wv.w);
            #pragma unroll
            for (int mq = 0; mq < 4; mq++) {
                acc[0][mq] = fma2(w0, xv[mq], acc[0][mq]);
                acc[1][mq] = fma2(w1, xv[mq], acc[1][mq]);
                acc[2][mq] = fma2(w2, xv[mq], acc[2][mq]);
                acc[3][mq] = fma2(w3, xv[mq], acc[3][mq]);
            }
        }
        __syncthreads();
    }

    float* Lb = g_logits + ng * 230400;
    #pragma unroll
    for (int dd = 0; dd < 4; dd++) {
        const int wpos = d0 + td * 4 + dd;
        if (wpos >= 225) continue;
        const float bv = brel[g * 225 + wpos];
        const int dy = wpos / 15;
        const int dxw = wpos - dy * 15;
        #pragma unroll
        for (int mq = 0; mq < 4; mq++) {
            const int pix = pix0 + 2 * tm + 32 * mq;
            const int y = pix >> 5, x = pix & 31;
            const int iy = y + dy - 7;
            const bool ry = (iy >= 0) && (iy < 32);
            const int ix0 = x + dxw - 7;
            float2 t = unpack2(acc[dd][mq]);
            float v0 = (ry && ix0 >= 0 && ix0 < 32) ? t.x + bv : -1e8f;
            float v1 = (ry && ix0 + 1 >= 0 && ix0 + 1 < 32) ? t.y + bv : -1e8f;
            *(float2*)(Lb + wpos * 1024 + pix) = make_float2(v0, v1);
        }
    }
}

// ---------------------------------------------------------------------------
// QK-add kernel: adds (q/T).k into g_logits. Reads g_qT (pre-scaled), g_kT.
// ---------------------------------------------------------------------------
constexpr int QK_Q0   = 0;
constexpr int QK_Q1   = 32 * 132;
constexpr int QK_SLAB = 2 * 32 * 132;
constexpr int QK_SMEM_FLOATS = QK_SLAB + 46 * 132;
constexpr int QK_SMEM_BYTES  = QK_SMEM_FLOATS * 4;

__global__ void __launch_bounds__(256) qk_kernel() {
    extern __shared__ float sm[];
    float* q0s  = sm + QK_Q0;
    float* q1s  = sm + QK_Q1;
    float* slab = sm + QK_SLAB;

    const int yp = blockIdx.x;
    const int y0 = yp * 2, y1 = y0 + 1;
    const int h  = blockIdx.y;
    const int d0 = h ? 8 : 0;
    const int d1 = h ? 15 : 8;
    const int ng = blockIdx.z;
    const int tid = threadIdx.x;
    const int x = tid & 31, w = tid >> 5;

    const float* qT = g_qT + ng * 131072;
    const float* kT = g_kT + ng * 131072;
    float* Lb = g_logits + ng * 230400;

    for (int i = tid; i < 1024; i += 256) {
        int xx = i >> 5, c4 = i & 31;
        *(float4*)(q0s + xx * 132 + c4 * 4) =
            *(const float4*)(qT + (y0 * 32 + xx) * 128 + c4 * 4);
        *(float4*)(q1s + xx * 132 + c4 * 4) =
            *(const float4*)(qT + (y1 * 32 + xx) * 128 + c4 * 4);
    }
    for (int i = tid; i < 14 * 32; i += 256) {
        int e = i >> 5, c4 = i & 31;
        int px = (e < 7) ? e : e + 32;
        *(float4*)(slab + px * 132 + c4 * 4) = make_float4(0.f, 0.f, 0.f, 0.f);
    }

    const int dx0 = w;
    const int dx1 = (w < 7) ? w + 8 : 0;
    const int Rlo = y0 + d0 - 7;
    const int Rhi = y0 + d1 - 7;

    for (int R = Rlo; R <= Rhi; R++) {
        if (R < 0 || R > 31) continue;
        __syncthreads();
        for (int i = tid; i < 1024; i += 256) {
            int ix = i >> 5, c4 = i & 31;
            *(float4*)(slab + (ix + 7) * 132 + c4 * 4) =
                *(const float4*)(kT + (R * 32 + ix) * 128 + c4 * 4);
        }
        __syncthreads();

        u64 a00 = 0, a01 = 0, a10 = 0, a11 = 0;
        const float* qp0 = q0s + x * 132;
        const float* qp1 = q1s + x * 132;
        const float* k0p = slab + (x + dx0) * 132;
        const float* k1p = slab + (x + dx1) * 132;
        #pragma unroll 8
        for (int c4 = 0; c4 < 32; c4++) {
            ulonglong2 q0v = *(const ulonglong2*)(qp0 + 4 * c4);
            ulonglong2 q1v = *(const ulonglong2*)(qp1 + 4 * c4);
            ulonglong2 k0v = *(const ulonglong2*)(k0p + 4 * c4);
            ulonglong2 k1v = *(const ulonglong2*)(k1p + 4 * c4);
            a00 = fma2(q0v.x, k0v.x, a00); a00 = fma2(q0v.y, k0v.y, a00);
            a01 = fma2(q0v.x, k1v.x, a01); a01 = fma2(q0v.y, k1v.y, a01);
            a10 = fma2(q1v.x, k0v.x, a10); a10 = fma2(q1v.y, k0v.y, a10);
            a11 = fma2(q1v.x, k1v.x, a11); a11 = fma2(q1v.y, k1v.y, a11);
        }

        const int dyA = R - y0 + 7;
        const int dyB = dyA - 1;
        if (dyA >= d0 && dyA < d1) {
            float2 t = unpack2(a00);
            Lb[(dyA * 15 + dx0) * 1024 + y0 * 32 + x] += t.x + t.y;
            if (w < 7) {
                float2 u = unpack2(a01);
                Lb[(dyA * 15 + dx1) * 1024 + y0 * 32 + x] += u.x + u.y;
            }
        }
        if (dyB >= d0 && dyB < d1) {
            float2 t = unpack2(a10);
            Lb[(dyB * 15 + dx0) * 1024 + y1 * 32 + x] += t.x + t.y;
            if (w < 7) {
                float2 u = unpack2(a11);
                Lb[(dyB * 15 + dx1) * 1024 + y1 * 32 + x] += u.x + u.y;
            }
        }
    }
}

// ---------------------------------------------------------------------------
// Softmax over wpos (in place on g_logits). grid (4, 8), 256 threads.
// ---------------------------------------------------------------------------
__global__ void __launch_bounds__(256) softmax_kernel() {
    const int pix = blockIdx.x * 256 + threadIdx.x;
    float* base = g_logits + blockIdx.y * 230400 + pix;
    float m = -1e30f;
    for (int w = 0; w < 225; w++) m = fmaxf(m, base[w * 1024]);
    float s = 0.f;
    for (int w = 0; w < 225; w++) {
        float e = __expf(base[w * 1024] - m);
        base[w * 1024] = e;
        s += e;
    }
    float r = 1.f / s;
    for (int w = 0; w < 225; w++) base[w * 1024] *= r;
}

// ---------------------------------------------------------------------------
// Bias GEMM: g_agg[(pix*4+n)*256 + g*128 + c] = sum_w attn[w][pix]*VbT[w][c]
// Tile 64 pix x 128 c. grid (16 pixtile, 8 ng).
// ---------------------------------------------------------------------------
__global__ void __launch_bounds__(256) bias_kernel() {
    __shared__ float a_s[32 * 72];    // [kk][pix]
    __shared__ float b_s[32 * 128];   // [kk][c]

    const int pix0 = blockIdx.x * 64;
    const int ng   = blockIdx.y;
    const int g    = ng & 1, n = ng >> 1;
    const int tid  = threadIdx.x;

    const float* attn = g_logits + ng * 230400;
    const float* vbt  = g_VbT + g * 28800;

    const int td = tid >> 4;   // pix rows td*4+dd
    const int tm = tid & 15;   // c cols 2tm+32mq

    u64 acc[4][4];
    #pragma unroll
    for (int dd = 0; dd < 4; dd++)
        #pragma unroll
        for (int mq = 0; mq < 4; mq++) acc[dd][mq] = 0ull;

    const float4 z4 = make_float4(0.f, 0.f, 0.f, 0.f);

    for (int kb = 0; kb < 8; kb++) {
        const int k0 = kb * 32;
        #pragma unroll
        for (int r = 0; r < 2; r++) {
            int idx = tid + r * 256;          // 512 float4 slots
            int kk = idx >> 4, p4 = idx & 15;
            int w = k0 + kk;
            float4 v = (w < 225)
                ? *(const float4*)(attn + w * 1024 + pix0 + p4 * 4) : z4;
            *(float4*)(a_s + kk * 72 + p4 * 4) = v;
        }
        #pragma unroll
        for (int r = 0; r < 4; r++) {
            int idx = tid + r * 256;          // 1024 float4 slots
            int kk = idx >> 5, c4 = idx & 31;
            int w = k0 + kk;
            float4 v = (w < 225)
                ? *(const float4*)(vbt + w * 128 + c4 * 4) : z4;
            *(float4*)(b_s + kk * 128 + c4 * 4) = v;
        }
        __syncthreads();

        #pragma unroll 8
        for (int kk = 0; kk < 32; kk++) {
            float4 av = *(const float4*)(a_s + kk * 72 + td * 4);
            u64 xv[4];
            #pragma unroll
            for (int mq = 0; mq < 4; mq++)
                xv[mq] = *(const u64*)(b_s + kk * 128 + 2 * tm + 32 * mq);
            u64 w0 = pack2(av.x, av.x), w1 = pack2(av.y, av.y);
            u64 w2 = pack2(av.z, av.z), w3 = pack2(av.w, av.w);
            #pragma unroll
            for (int mq = 0; mq < 4; mq++) {
                acc[0][mq] = fma2(w0, xv[mq], acc[0][mq]);
                acc[1][mq] = fma2(w1, xv[mq], acc[1][mq]);
                acc[2][mq] = fma2(w2, xv[mq], acc[2][mq]);
                acc[3][mq] = fma2(w3, xv[mq], acc[3][mq]);
            }
        }
        __syncthreads();
    }

    #pragma unroll
    for (int dd = 0; dd < 4; dd++) {
        const int pix = pix0 + td * 4 + dd;
        float* ap = g_agg + (pix * 4 + n) * 256 + g * 128 + 2 * tm;
        #pragma unroll
        for (int mq = 0; mq < 4; mq++)
            *(float2*)(ap + 32 * mq) = unpack2(acc[dd][mq]);
    }
}

// ---------------------------------------------------------------------------
// V aggregation: g_agg += sum_w attn[w][pix] * V_unfold.  grid (32 y, 2 g, 4 n).
// ---------------------------------------------------------------------------
constexpr int AG_SLAB = 7200;                       // attn first
constexpr int AG_SMEM_FLOATS = 7200 + 46 * 132;     // 13272
constexpr int AG_SMEM_BYTES  = AG_SMEM_FLOATS * 4;  // 53088

__global__ void __launch_bounds__(256) agg_kernel() {
    extern __shared__ float sm[];
    float* att  = sm;
    float* slab = sm + AG_SLAB;

    const int y = blockIdx.x, g = blockIdx.y, n = blockIdx.z;
    const int ng = n * 2 + g;
    const int tid = threadIdx.x;
    const int x = tid & 31, w = tid >> 5;
    const int cbase = w * 16;

    const float* vT = g_vT + ng * 131072;
    const float* Lb = g_logits + ng * 230400;

    // attn [225][32]
    for (int i = tid; i < 1800; i += 256) {
        int ww = i >> 3, x4 = i & 7;
        *(float4*)(att + ww * 32 + x4 * 4) =
            *(const float4*)(Lb + ww * 1024 + y * 32 + x4 * 4);
    }
    // permanent zero edges of slab
    for (int i = tid; i < 14 * 32; i += 256) {
        int e = i >> 5, c4 = i & 31;
        int px = (e < 7) ? e : e + 32;
        *(float4*)(slab + px * 132 + c4 * 4) = make_float4(0.f, 0.f, 0.f, 0.f);
    }

    u64 acc[8];
    #pragma unroll
    for (int j = 0; j < 8; j++) acc[j] = 0;

    for (int dy = 0; dy < 15; dy++) {
        const int iy = y + dy - 7;
        if (iy < 0 || iy >= 32) continue;     // attn there is exactly 0
        __syncthreads();
        for (int i = tid; i < 1024; i += 256) {
            int ix = i >> 5, c4 = i & 31;
            *(float4*)(slab + (ix + 7) * 132 + c4 * 4) =
                *(const float4*)(vT + (iy * 32 + ix) * 128 + c4 * 4);
        }
        __syncthreads();

        const float* awrow = att + dy * 15 * 32 + x;
        #pragma unroll 5
        for (int dx = 0; dx < 15; dx++) {
            float aw = awrow[dx * 32];
            u64 aw2 = pack2(aw, aw);
            const float* vp = slab + (x + dx) * 132 + cbase;
            #pragma unroll
            for (int j = 0; j < 4; j++) {
                ulonglong2 vv = *(const ulonglong2*)(vp + 4 * j);
                acc[2 * j]     = fma2(aw2, vv.x, acc[2 * j]);
                acc[2 * j + 1] = fma2(aw2, vv.y, acc[2 * j + 1]);
            }
        }
    }

    float* ap = g_agg + ((y * 32 + x) * 4 + n) * 256 + g * 128 + cbase;
    #pragma unroll
    for (int j = 0; j < 8; j++) {
        float2 o = *(float2*)(ap + 2 * j);
        float2 t = unpack2(acc[j]);
        *(float2*)(ap + 2 * j) = make_float2(o.x + t.x, o.y + t.y);
    }
}

// ---------------------------------------------------------------------------
// Output FC
// ---------------------------------------------------------------------------
__global__ void __launch_bounds__(256) fc_kernel(
        const float* __restrict__ Wfc, const float* __restrict__ bfc,
        float* __restrict__ out) {
    __shared__ float w_s[32 * 68];
    __shared__ float x_s[32 * 128];

    const int r0 = blockIdx.x * 64;
    const int d0 = blockIdx.y * 128;
    const int tid = threadIdx.x;
    const int td = tid >> 4;
    const int tm = tid & 15;

    u64 acc[4][4];
    #pragma unroll
    for (int mq = 0; mq < 4; mq++) {
        int d = d0 + 2 * tm + 32 * mq;
        u64 bb = pack2(bfc[d], bfc[d + 1]);
        #pragma unroll
        for (int rr = 0; rr < 4; rr++) acc[rr][mq] = bb;
    }

    const int lrq = tid >> 3;
    const int lc4 = tid & 7;
    const int ld  = tid & 127;
    const int lch = tid >> 7;

    for (int kb = 0; kb < 8; kb++) {
        const int k0 = kb * 32;
        {
            float4 fa = *(const float4*)(g_agg + (r0 + lrq) * 256 + k0 + lc4 * 4);
            float4 fb = *(const float4*)(g_agg + (r0 + lrq + 32) * 256 + k0 + lc4 * 4);
            w_s[(lc4 * 4 + 0) * 68 + lrq] = fa.x;
            w_s[(lc4 * 4 + 1) * 68 + lrq] = fa.y;
            w_s[(lc4 * 4 + 2) * 68 + lrq] = fa.z;
            w_s[(lc4 * 4 + 3) * 68 + lrq] = fa.w;
            w_s[(lc4 * 4 + 0) * 68 + lrq + 32] = fb.x;
            w_s[(lc4 * 4 + 1) * 68 + lrq + 32] = fb.y;
            w_s[(lc4 * 4 + 2) * 68 + lrq + 32] = fb.z;
            w_s[(lc4 * 4 + 3) * 68 + lrq + 32] = fb.w;
        }
        #pragma unroll
        for (int i = 0; i < 4; i++) {
            int cq = lch * 4 + i;
            float4 f = *(const float4*)(Wfc + (d0 + ld) * 256 + k0 + cq * 4);
            x_s[(cq * 4 + 0) * 128 + ld] = f.x;
            x_s[(cq * 4 + 1) * 128 + ld] = f.y;
            x_s[(cq * 4 + 2) * 128 + ld] = f.z;
            x_s[(cq * 4 + 3) * 128 + ld] = f.w;
        }
        __syncthreads();

        #pragma unroll 8
        for (int kk = 0; kk < 32; kk++) {
            float4 wv = *(const float4*)(w_s + kk * 68 + td * 4);
            u64 xv[4];
            #pragma unroll
            for (int mq = 0; mq < 4; mq++)
                xv[mq] = *(const u64*)(x_s + kk * 128 + 2 * tm + 32 * mq);
            u64 w0 = pack2(wv.x, wv.x), w1 = pack2(wv.y, wv.y);
            u64 w2 = pack2(wv.z, wv.z), w3 = pack2(wv.w, wv.w);
            #pragma unroll
            for (int mq = 0; mq < 4; mq++) {
                acc[0][mq] = fma2(w0, xv[mq], acc[0][mq]);
                acc[1][mq] = fma2(w1, xv[mq], acc[1][mq]);
                acc[2][mq] = fma2(w2, xv[mq], acc[2][mq]);
                acc[3][mq] = fma2(w3, xv[mq], acc[3][mq]);
            }
        }
        __syncthreads();
    }

    #pragma unroll
    for (int rr = 0; rr < 4; rr++) {
        float* op = out + (r0 + td * 4 + rr) * 256 + d0 + 2 * tm;
        #pragma unroll
        for (int mq = 0; mq < 4; mq++)
            *(float2*)(op + 32 * mq) = unpack2(acc[rr][mq]);
    }
}

// ---------------------------------------------------------------------------
extern "C" void kernel_launch(void* const* d_in, const int* in_sizes, int n_in,
                              void* d_out, int out_size) {
    const float* q    = (const float*)d_in[0];
    const float* k    = (const float*)d_in[1];
    const float* v    = (const float*)d_in[2];
    const float* Wq   = (const float*)d_in[3];
    const float* bq   = (const float*)d_in[4];
    const float* Wk   = (const float*)d_in[5];
    const float* bk   = (const float*)d_in[6];
    const float* Wv   = (const float*)d_in[7];
    const float* bv   = (const float*)d_in[8];
    const float* Wrel = (const float*)d_in[9];
    const float* brel = (const float*)d_in[10];
    const float* Vb   = (const float*)d_in[11];
    const float* Wfc  = (const float*)d_in[12];
    const float* bfc  = (const float*)d_in[13];
    float* out = (float*)d_out;

    cudaFuncSetAttribute(qk_kernel, cudaFuncAttributeMaxDynamicSharedMemorySize,
                         QK_SMEM_BYTES);
    cudaFuncSetAttribute(agg_kernel, cudaFuncAttributeMaxDynamicSharedMemorySize,
                         AG_SMEM_BYTES);

    dim3 pg(32, 4, 3);
    proj_kernel<<<pg, 128>>>(q, k, v, Wq, bq, Wk, bk, Wv, bv);

    dim3 tg(32, 4, 24);
    transpose_kernel<<<tg, 256>>>();

    dim3 vg(113, 2);
    vbt_kernel<<<vg, 256>>>(Vb);

    dim3 rg(8, 4, 8);
    rel_kernel<<<rg, 256>>>(Wrel, brel);

    dim3 qg(16, 2, 8);
    qk_kernel<<<qg, 256, QK_SMEM_BYTES>>>();

    dim3 sg(4, 8);
    softmax_kernel<<<sg, 256>>>();

    dim3 bg(16, 8);
    bias_kernel<<<bg, 256>>>();

    dim3 ag(32, 2, 4);
    agg_kernel<<<ag, 256, AG_SMEM_BYTES>>>();

    dim3 fg(64, 2);
    fc_kernel<<<fg, 256>>>(Wfc, bfc, out);
}

// round 6
// speedup vs baseline: 1.1022x; 1.1022x over previous
#include <cuda_runtime.h>

typedef unsigned long long u64;

// ---------------- f32x2 packed-math helpers (sm_103a) ----------------
__device__ __forceinline__ u64 fma2(u64 a, u64 b, u64 c) {
    u64 d;
    asm("fma.rn.f32x2 %0, %1, %2, %3;" : "=l"(d) : "l"(a), "l"(b), "l"(c));
    return d;
}
__device__ __forceinline__ u64 add2(u64 a, u64 b) {
    u64 d;
    asm("add.rn.f32x2 %0, %1, %2;" : "=l"(d) : "l"(a), "l"(b));
    return d;
}
__device__ __forceinline__ u64 pack2(float lo, float hi) {
    u64 d;
    asm("mov.b64 %0, {%1, %2};" : "=l"(d) : "f"(lo), "f"(hi));
    return d;
}
__device__ __forceinline__ float2 unpack2(u64 v) {
    float2 r;
    asm("mov.b64 {%0, %1}, %2;" : "=f"(r.x), "=f"(r.y) : "l"(v));
    return r;
}

// Scratch (zero-initialized device globals)
__device__ float g_qproj[4 * 256 * 1024];   // [n][c][pix] (unscaled, for rel)
__device__ float g_qT[8 * 1024 * 128];      // [ng][pix][c], scaled by 1/T
__device__ float g_kT[8 * 1024 * 128];
__device__ float g_vT[8 * 1024 * 128];
__device__ float g_VbT[2 * 225 * 128];      // [g][w][c]
__device__ float g_agg[1024 * 4 * 256];
__device__ float g_logits[8 * 225 * 1024];  // [ng][wpos][pix]  rel / then attn
__device__ float g_qk[8 * 225 * 1024];      // [ng][wpos][pix]  raw qk dots

// ---------------------------------------------------------------------------
// proj: Y = W.X + b ; writes qT/kT/vT (transposed, q scaled) + qproj.
// z = 3 slice transposes V_bias. 128 threads, tile 64d x 128m, micro 8x8.
// ---------------------------------------------------------------------------
__global__ void __launch_bounds__(128) proj_kernel(
        const float* __restrict__ q, const float* __restrict__ k,
        const float* __restrict__ v,
        const float* __restrict__ Wq, const float* __restrict__ bq,
        const float* __restrict__ Wk, const float* __restrict__ bk,
        const float* __restrict__ Wv, const float* __restrict__ bv,
        const float* __restrict__ Vb) {
    __shared__ float w_s[32 * 68];    // [kk][d]
    __shared__ float x_s[32 * 128];   // [kk][m]

    const int p   = blockIdx.z;
    const int tid = threadIdx.x;

    if (p == 3) {   // V_bias transpose: [g][c][w] -> [g][w][c]
        int idx = (blockIdx.x * 4 + blockIdx.y) * 128 + tid;
        for (int i = idx; i < 57600; i += 16384) {
            int g = i / 28800, r = i - g * 28800;
            int w = r >> 7, c = r & 127;
            g_VbT[g * 28800 + r] = Vb[g * 28800 + c * 225 + w];
        }
        return;
    }

    const int m0 = blockIdx.x * 128;
    const int d0 = blockIdx.y * 64;
    const int n  = m0 >> 10;
    const int hw0 = m0 & 1023;

    const float *X, *Wm, *B;
    if (p == 0)      { X = q; Wm = Wq; B = bq; }
    else if (p == 1) { X = k; Wm = Wk; B = bk; }
    else             { X = v; Wm = Wv; B = bv; }

    const int td = tid >> 4;   // 0..7 -> d rows td*8..+7
    const int tm = tid & 15;   // m cols 2tm+32mq

    u64 acc[8][4];
    #pragma unroll
    for (int dd = 0; dd < 8; dd++) {
        float b = B[d0 + td * 8 + dd];
        u64 bb = pack2(b, b);
        #pragma unroll
        for (int mq = 0; mq < 4; mq++) acc[dd][mq] = bb;
    }

    const int dl   = tid >> 1;
    const int half = tid & 1;

    for (int kb = 0; kb < 8; kb++) {
        const int k0 = kb * 32;
        {
            const float* src = Wm + (d0 + dl) * 256 + k0 + half * 16;
            #pragma unroll
            for (int qq = 0; qq < 4; qq++) {
                float4 f = *(const float4*)(src + qq * 4);
                int kk = half * 16 + qq * 4;
                w_s[(kk + 0) * 68 + dl] = f.x;
                w_s[(kk + 1) * 68 + dl] = f.y;
                w_s[(kk + 2) * 68 + dl] = f.z;
                w_s[(kk + 3) * 68 + dl] = f.w;
            }
        }
        #pragma unroll
        for (int r = 0; r < 8; r++) {
            int idx = tid + r * 128;
            int kk = idx >> 5, m4 = idx & 31;
            *(float4*)(x_s + kk * 128 + m4 * 4) =
                *(const float4*)(X + (n * 256 + k0 + kk) * 1024 + hw0 + m4 * 4);
        }
        __syncthreads();

        #pragma unroll 8
        for (int kk = 0; kk < 32; kk++) {
            float4 wa = *(const float4*)(w_s + kk * 68 + td * 8);
            float4 wb = *(const float4*)(w_s + kk * 68 + td * 8 + 4);
            u64 xv[4];
            #pragma unroll
            for (int mq = 0; mq < 4; mq++)
                xv[mq] = *(const u64*)(x_s + kk * 128 + 2 * tm + 32 * mq);
            u64 wr[8];
            wr[0] = pack2(wa.x, wa.x); wr[1] = pack2(wa.y, wa.y);
            wr[2] = pack2(wa.z, wa.z); wr[3] = pack2(wa.w, wa.w);
            wr[4] = pack2(wb.x, wb.x); wr[5] = pack2(wb.y, wb.y);
            wr[6] = pack2(wb.z, wb.z); wr[7] = pack2(wb.w, wb.w);
            #pragma unroll
            for (int dd = 0; dd < 8; dd++)
                #pragma unroll
                for (int mq = 0; mq < 4; mq++)
                    acc[dd][mq] = fma2(wr[dd], xv[mq], acc[dd][mq]);
        }
        __syncthreads();
    }

    // transposed store -> [ng][pix][c]
    const int gg  = d0 >> 7;
    const int ng  = n * 2 + gg;
    const int ch0 = (d0 & 127) + td * 8;
    float* T = (p == 0) ? g_qT : (p == 1) ? g_kT : g_vT;
    const float s = (p == 0) ? 0.08838834764831845f : 1.f;
    #pragma unroll
    for (int mq = 0; mq < 4; mq++) {
        float2 t[8];
        #pragma unroll
        for (int dd = 0; dd < 8; dd++) t[dd] = unpack2(acc[dd][mq]);
        float* b0 = T + ng * 131072 + (hw0 + 2 * tm + 32 * mq) * 128 + ch0;
        *(float4*)(b0)       = make_float4(t[0].x*s, t[1].x*s, t[2].x*s, t[3].x*s);
        *(float4*)(b0 + 4)   = make_float4(t[4].x*s, t[5].x*s, t[6].x*s, t[7].x*s);
        *(float4*)(b0 + 128) = make_float4(t[0].y*s, t[1].y*s, t[2].y*s, t[3].y*s);
        *(float4*)(b0 + 132) = make_float4(t[4].y*s, t[5].y*s, t[6].y*s, t[7].y*s);
    }
    if (p == 0) {   // [c][pix] copy for rel GEMM
        #pragma unroll
        for (int dd = 0; dd < 8; dd++) {
            float* yp = g_qproj + (n * 256 + d0 + td * 8 + dd) * 1024 + hw0 + 2 * tm;
            #pragma unroll
            for (int mq = 0; mq < 4; mq++)
                *(float2*)(yp + 32 * mq) = unpack2(acc[dd][mq]);
        }
    }
}

// ---------------------------------------------------------------------------
// Fused rel-GEMM + QK kernel. bid < 256: rel -> g_logits (masked, +brel).
// bid >= 256: qk dots -> g_qk.
// ---------------------------------------------------------------------------
constexpr int QK_SMEM_FLOATS = 2 * 32 * 132 + 46 * 132;   // 14520
constexpr int QK_SMEM_BYTES  = QK_SMEM_FLOATS * 4;        // 58080

__device__ void rel_body(float* sm, int bid,
                         const float* __restrict__ Wrel,
                         const float* __restrict__ brel) {
    float* w_s = sm;            // 32*68
    float* x_s = sm + 2176;     // 32*128

    const int pix0 = (bid & 7) * 128;
    const int d0   = ((bid >> 3) & 3) * 64;
    const int ng   = bid >> 5;
    const int g    = ng & 1;
    const int tid  = threadIdx.x;

    const float* Wg = Wrel + g * 225 * 128;
    const float* X  = g_qproj + ng * 131072;

    const int td = tid >> 4;
    const int tm = tid & 15;

    u64 acc[4][4];
    #pragma unroll
    for (int dd = 0; dd < 4; dd++)
        #pragma unroll
        for (int mq = 0; mq < 4; mq++) acc[dd][mq] = 0ull;

    const int ldq = tid >> 3;
    const int lc4 = tid & 7;
    const int lk  = tid >> 5;
    const int lm4 = tid & 31;

    for (int kb = 0; kb < 4; kb++) {
        const int k0 = kb * 32;
        {
            float4 z = make_float4(0.f, 0.f, 0.f, 0.f);
            float4 fa = (d0 + ldq < 225)
                ? *(const float4*)(Wg + (d0 + ldq) * 128 + k0 + lc4 * 4) : z;
            float4 fb = (d0 + ldq + 32 < 225)
                ? *(const float4*)(Wg + (d0 + ldq + 32) * 128 + k0 + lc4 * 4) : z;
            w_s[(lc4 * 4 + 0) * 68 + ldq] = fa.x;
            w_s[(lc4 * 4 + 1) * 68 + ldq] = fa.y;
            w_s[(lc4 * 4 + 2) * 68 + ldq] = fa.z;
            w_s[(lc4 * 4 + 3) * 68 + ldq] = fa.w;
            w_s[(lc4 * 4 + 0) * 68 + ldq + 32] = fb.x;
            w_s[(lc4 * 4 + 1) * 68 + ldq + 32] = fb.y;
            w_s[(lc4 * 4 + 2) * 68 + ldq + 32] = fb.z;
            w_s[(lc4 * 4 + 3) * 68 + ldq + 32] = fb.w;
        }
        #pragma unroll
        for (int r = 0; r < 4; r++) {
            *(float4*)(x_s + (lk + 8 * r) * 128 + lm4 * 4) =
                *(const float4*)(X + (k0 + lk + 8 * r) * 1024 + pix0 + lm4 * 4);
        }
        __syncthreads();

        #pragma unroll 8
        for (int kk = 0; kk < 32; kk++) {
            float4 wv = *(const float4*)(w_s + kk * 68 + td * 4);
            u64 xv[4];
            #pragma unroll
            for (int mq = 0; mq < 4; mq++)
                xv[mq] = *(const u64*)(x_s + kk * 128 + 2 * tm + 32 * mq);
            u64 w0 = pack2(wv.x, wv.x), w1 = pack2(wv.y, wv.y);
            u64 w2 = pack2(wv.z, wv.z), w3 = pack2(wv.w, wv.w);
            #pragma unroll
            for (int mq = 0; mq < 4; mq++) {
                acc[0][mq] = fma2(w0, xv[mq], acc[0][mq]);
                acc[1][mq] = fma2(w1, xv[mq], acc[1][mq]);
                acc[2][mq] = fma2(w2, xv[mq], acc[2][mq]);
                acc[3][mq] = fma2(w3, xv[mq], acc[3][mq]);
            }
        }
        __syncthreads();
    }

    float* Lb = g_logits + ng * 230400;
    #pragma unroll
    for (int dd = 0; dd < 4; dd++) {
        const int wpos = d0 + td * 4 + dd;
        if (wpos >= 225) continue;
        const float bv = brel[g * 225 + wpos];
        const int dy = wpos / 15;
        const int dxw = wpos - dy * 15;
        #pragma unroll
        for (int mq = 0; mq < 4; mq++) {
            const int pix = pix0 + 2 * tm + 32 * mq;
            const int y = pix >> 5, x = pix & 31;
            const int iy = y + dy - 7;
            const bool ry = (iy >= 0) && (iy < 32);
            const int ix0 = x + dxw - 7;
            float2 t = unpack2(acc[dd][mq]);
            float v0 = (ry && ix0 >= 0 && ix0 < 32) ? t.x + bv : -1e8f;
            float v1 = (ry && ix0 + 1 >= 0 && ix0 + 1 < 32) ? t.y + bv : -1e8f;
            *(float2*)(Lb + wpos * 1024 + pix) = make_float2(v0, v1);
        }
    }
}

__device__ void qk_body(float* sm, int b) {
    float* q0s  = sm;
    float* q1s  = sm + 32 * 132;
    float* slab = sm + 2 * 32 * 132;

    const int yp = b & 15;
    const int y0 = yp * 2, y1 = y0 + 1;
    const int h  = (b >> 4) & 1;
    const int d0 = h ? 8 : 0;
    const int d1 = h ? 15 : 8;
    const int ng = b >> 5;
    const int tid = threadIdx.x;
    const int x = tid & 31, w = tid >> 5;

    const float* qT = g_qT + ng * 131072;
    const float* kT = g_kT + ng * 131072;
    float* Qb = g_qk + ng * 230400;

    for (int i = tid; i < 1024; i += 256) {
        int xx = i >> 5, c4 = i & 31;
        *(float4*)(q0s + xx * 132 + c4 * 4) =
            *(const float4*)(qT + (y0 * 32 + xx) * 128 + c4 * 4);
        *(float4*)(q1s + xx * 132 + c4 * 4) =
            *(const float4*)(qT + (y1 * 32 + xx) * 128 + c4 * 4);
    }
    for (int i = tid; i < 14 * 32; i += 256) {
        int e = i >> 5, c4 = i & 31;
        int px = (e < 7) ? e : e + 32;
        *(float4*)(slab + px * 132 + c4 * 4) = make_float4(0.f, 0.f, 0.f, 0.f);
    }

    const int dx0 = w;
    const int dx1 = (w < 7) ? w + 8 : 0;
    const int Rlo = y0 + d0 - 7;
    const int Rhi = y0 + d1 - 7;

    for (int R = Rlo; R <= Rhi; R++) {
        if (R < 0 || R > 31) continue;
        __syncthreads();
        for (int i = tid; i < 1024; i += 256) {
            int ix = i >> 5, c4 = i & 31;
            *(float4*)(slab + (ix + 7) * 132 + c4 * 4) =
                *(const float4*)(kT + (R * 32 + ix) * 128 + c4 * 4);
        }
        __syncthreads();

        u64 a00 = 0, a01 = 0, a10 = 0, a11 = 0;
        const float* qp0 = q0s + x * 132;
        const float* qp1 = q1s + x * 132;
        const float* k0p = slab + (x + dx0) * 132;
        const float* k1p = slab + (x + dx1) * 132;
        #pragma unroll 8
        for (int c4 = 0; c4 < 32; c4++) {
            ulonglong2 q0v = *(const ulonglong2*)(qp0 + 4 * c4);
            ulonglong2 q1v = *(const ulonglong2*)(qp1 + 4 * c4);
            ulonglong2 k0v = *(const ulonglong2*)(k0p + 4 * c4);
            ulonglong2 k1v = *(const ulonglong2*)(k1p + 4 * c4);
            a00 = fma2(q0v.x, k0v.x, a00); a00 = fma2(q0v.y, k0v.y, a00);
            a01 = fma2(q0v.x, k1v.x, a01); a01 = fma2(q0v.y, k1v.y, a01);
            a10 = fma2(q1v.x, k0v.x, a10); a10 = fma2(q1v.y, k0v.y, a10);
            a11 = fma2(q1v.x, k1v.x, a11); a11 = fma2(q1v.y, k1v.y, a11);
        }

        const int dyA = R - y0 + 7;
        const int dyB = dyA - 1;
        if (dyA >= d0 && dyA < d1) {
            float2 t = unpack2(a00);
            Qb[(dyA * 15 + dx0) * 1024 + y0 * 32 + x] = t.x + t.y;
            if (w < 7) {
                float2 u = unpack2(a01);
                Qb[(dyA * 15 + dx1) * 1024 + y0 * 32 + x] = u.x + u.y;
            }
        }
        if (dyB >= d0 && dyB < d1) {
            float2 t = unpack2(a10);
            Qb[(dyB * 15 + dx0) * 1024 + y1 * 32 + x] = t.x + t.y;
            if (w < 7) {
                float2 u = unpack2(a11);
                Qb[(dyB * 15 + dx1) * 1024 + y1 * 32 + x] = u.x + u.y;
            }
        }
    }
}

__global__ void __launch_bounds__(256) relqk_kernel(
        const float* __restrict__ Wrel, const float* __restrict__ brel) {
    extern __shared__ float sm[];
    const int bid = blockIdx.x;
    if (bid < 256) rel_body(sm, bid, Wrel, brel);
    else           qk_body(sm, bid - 256);
}

// ---------------------------------------------------------------------------
// Softmax: attn = softmax_w(g_logits + g_qk), written back to g_logits.
// Block per (y, ng). 256 threads.
// ---------------------------------------------------------------------------
__global__ void __launch_bounds__(256) softmax_kernel() {
    __shared__ float att[7200];
    __shared__ float red[256];
    const int y = blockIdx.x, ng = blockIdx.y;
    const int tid = threadIdx.x;
    const int x = tid & 31, w = tid >> 5;
    float* L = g_logits + ng * 230400;
    const float* Q = g_qk + ng * 230400;

    for (int i = tid; i < 1800; i += 256) {
        int ww = i >> 3, x4 = i & 7;
        float4 a = *(const float4*)(L + ww * 1024 + y * 32 + x4 * 4);
        float4 b = *(const float4*)(Q + ww * 1024 + y * 32 + x4 * 4);
        *(float4*)(att + ww * 32 + x4 * 4) =
            make_float4(a.x + b.x, a.y + b.y, a.z + b.z, a.w + b.w);
    }
    __syncthreads();

    float lm = -1e30f;
    for (int ww = w; ww < 225; ww += 8) lm = fmaxf(lm, att[ww * 32 + x]);
    red[w * 32 + x] = lm;
    __syncthreads();
    float m = red[x];
    #pragma unroll
    for (int i = 1; i < 8; i++) m = fmaxf(m, red[i * 32 + x]);
    __syncthreads();
    float ls = 0.f;
    for (int ww = w; ww < 225; ww += 8) {
        float e = __expf(att[ww * 32 + x] - m);
        att[ww * 32 + x] = e;
        ls += e;
    }
    red[w * 32 + x] = ls;
    __syncthreads();
    float s = red[x];
    #pragma unroll
    for (int i = 1; i < 8; i++) s += red[i * 32 + x];
    float rinv = 1.f / s;
    for (int ww = w; ww < 225; ww += 8) att[ww * 32 + x] *= rinv;
    __syncthreads();

    for (int i = tid; i < 1800; i += 256) {
        int ww = i >> 3, x4 = i & 7;
        *(float4*)(L + ww * 1024 + y * 32 + x4 * 4) =
            *(const float4*)(att + ww * 32 + x4 * 4);
    }
}

// ---------------------------------------------------------------------------
// biasagg: g_agg = sum_w attn[w][pix] * (V_unfold + V_bias broadcast).
// Block per (y, g, n). Vb aux reads are warp-uniform (free broadcast).
// ---------------------------------------------------------------------------
constexpr int BA_ATT  = 0;
constexpr int BA_SLAB = 7200;
constexpr int BA_AUX  = 7200 + 46 * 132;
constexpr int BA_FLOATS = BA_AUX + 15 * 132;      // 15252
constexpr int BA_BYTES  = BA_FLOATS * 4;          // 61008

__global__ void __launch_bounds__(256) biasagg_kernel() {
    extern __shared__ float sm[];
    float* att  = sm + BA_ATT;
    float* slab = sm + BA_SLAB;
    float* aux  = sm + BA_AUX;

    const int y = blockIdx.x, g = blockIdx.y, n = blockIdx.z;
    const int ng = n * 2 + g;
    const int tid = threadIdx.x;
    const int x = tid & 31, w = tid >> 5;
    const int cbase = w * 16;

    const float* vT  = g_vT + ng * 131072;
    const float* Lb  = g_logits + ng * 230400;
    const float* vbt = g_VbT + g * 28800;

    for (int i = tid; i < 1800; i += 256) {
        int ww = i >> 3, x4 = i & 7;
        *(float4*)(att + ww * 32 + x4 * 4) =
            *(const float4*)(Lb + ww * 1024 + y * 32 + x4 * 4);
    }
    for (int i = tid; i < 14 * 32; i += 256) {
        int e = i >> 5, c4 = i & 31;
        int px = (e < 7) ? e : e + 32;
        *(float4*)(slab + px * 132 + c4 * 4) = make_float4(0.f, 0.f, 0.f, 0.f);
    }

    u64 acc[8];
    #pragma unroll
    for (int j = 0; j < 8; j++) acc[j] = 0;

    for (int dy = 0; dy < 15; dy++) {
        const int iy = y + dy - 7;
        if (iy < 0 || iy >= 32) continue;      // attn exactly 0 on this row
        __syncthreads();
        for (int i = tid; i < 1024; i += 256) {
            int ix = i >> 5, c4 = i & 31;
            *(float4*)(slab + (ix + 7) * 132 + c4 * 4) =
                *(const float4*)(vT + (iy * 32 + ix) * 128 + c4 * 4);
        }
        for (int i = tid; i < 480; i += 256) {
            int dxx = i >> 5, c4 = i & 31;
            *(float4*)(aux + dxx * 132 + c4 * 4) =
                *(const float4*)(vbt + (dy * 15 + dxx) * 128 + c4 * 4);
        }
        __syncthreads();

        const float* awrow = att + dy * 15 * 32 + x;
        #pragma unroll 5
        for (int dx = 0; dx < 15; dx++) {
            float aw = awrow[dx * 32];
            u64 aw2 = pack2(aw, aw);
            const float* vp = slab + (x + dx) * 132 + cbase;
            const float* bp = aux + dx * 132 + cbase;
            #pragma unroll
            for (int j = 0; j < 4; j++) {
                ulonglong2 vv = *(const ulonglong2*)(vp + 4 * j);
                ulonglong2 bb = *(const ulonglong2*)(bp + 4 * j);
                acc[2 * j]     = fma2(aw2, add2(vv.x, bb.x), acc[2 * j]);
                acc[2 * j + 1] = fma2(aw2, add2(vv.y, bb.y), acc[2 * j + 1]);
            }
        }
    }

    float* ap = g_agg + ((y * 32 + x) * 4 + n) * 256 + g * 128 + cbase;
    #pragma unroll
    for (int j = 0; j < 8; j++) *(float2*)(ap + 2 * j) = unpack2(acc[j]);
}

// ---------------------------------------------------------------------------
// Output FC
// ---------------------------------------------------------------------------
__global__ void __launch_bounds__(256) fc_kernel(
        const float* __restrict__ Wfc, const float* __restrict__ bfc,
        float* __restrict__ out) {
    __shared__ float w_s[32 * 68];
    __shared__ float x_s[32 * 128];

    const int r0 = blockIdx.x * 64;
    const int d0 = blockIdx.y * 128;
    const int tid = threadIdx.x;
    const int td = tid >> 4;
    const int tm = tid & 15;

    u64 acc[4][4];
    #pragma unroll
    for (int mq = 0; mq < 4; mq++) {
        int d = d0 + 2 * tm + 32 * mq;
        u64 bb = pack2(bfc[d], bfc[d + 1]);
        #pragma unroll
        for (int rr = 0; rr < 4; rr++) acc[rr][mq] = bb;
    }

    const int lrq = tid >> 3;
    const int lc4 = tid & 7;
    const int ld  = tid & 127;
    const int lch = tid >> 7;

    for (int kb = 0; kb < 8; kb++) {
        const int k0 = kb * 32;
        {
            float4 fa = *(const float4*)(g_agg + (r0 + lrq) * 256 + k0 + lc4 * 4);
            float4 fb = *(const float4*)(g_agg + (r0 + lrq + 32) * 256 + k0 + lc4 * 4);
            w_s[(lc4 * 4 + 0) * 68 + lrq] = fa.x;
            w_s[(lc4 * 4 + 1) * 68 + lrq] = fa.y;
            w_s[(lc4 * 4 + 2) * 68 + lrq] = fa.z;
            w_s[(lc4 * 4 + 3) * 68 + lrq] = fa.w;
            w_s[(lc4 * 4 + 0) * 68 + lrq + 32] = fb.x;
            w_s[(lc4 * 4 + 1) * 68 + lrq + 32] = fb.y;
            w_s[(lc4 * 4 + 2) * 68 + lrq + 32] = fb.z;
            w_s[(lc4 * 4 + 3) * 68 + lrq + 32] = fb.w;
        }
        #pragma unroll
        for (int i = 0; i < 4; i++) {
            int cq = lch * 4 + i;
            float4 f = *(const float4*)(Wfc + (d0 + ld) * 256 + k0 + cq * 4);
            x_s[(cq * 4 + 0) * 128 + ld] = f.x;
            x_s[(cq * 4 + 1) * 128 + ld] = f.y;
            x_s[(cq * 4 + 2) * 128 + ld] = f.z;
            x_s[(cq * 4 + 3) * 128 + ld] = f.w;
        }
        __syncthreads();

        #pragma unroll 8
        for (int kk = 0; kk < 32; kk++) {
            float4 wv = *(const float4*)(w_s + kk * 68 + td * 4);
            u64 xv[4];
            #pragma unroll
            for (int mq = 0; mq < 4; mq++)
                xv[mq] = *(const u64*)(x_s + kk * 128 + 2 * tm + 32 * mq);
            u64 w0 = pack2(wv.x, wv.x), w1 = pack2(wv.y, wv.y);
            u64 w2 = pack2(wv.z, wv.z), w3 = pack2(wv.w, wv.w);
            #pragma unroll
            for (int mq = 0; mq < 4; mq++) {
                acc[0][mq] = fma2(w0, xv[mq], acc[0][mq]);
                acc[1][mq] = fma2(w1, xv[mq], acc[1][mq]);
                acc[2][mq] = fma2(w2, xv[mq], acc[2][mq]);
                acc[3][mq] = fma2(w3, xv[mq], acc[3][mq]);
            }
        }
        __syncthreads();
    }

    #pragma unroll
    for (int rr = 0; rr < 4; rr++) {
        float* op = out + (r0 + td * 4 + rr) * 256 + d0 + 2 * tm;
        #pragma unroll
        for (int mq = 0; mq < 4; mq++)
            *(float2*)(op + 32 * mq) = unpack2(acc[rr][mq]);
    }
}

// ---------------------------------------------------------------------------
extern "C" void kernel_launch(void* const* d_in, const int* in_sizes, int n_in,
                              void* d_out, int out_size) {
    const float* q    = (const float*)d_in[0];
    const float* k    = (const float*)d_in[1];
    const float* v    = (const float*)d_in[2];
    const float* Wq   = (const float*)d_in[3];
    const float* bq   = (const float*)d_in[4];
    const float* Wk   = (const float*)d_in[5];
    const float* bk   = (const float*)d_in[6];
    const float* Wv   = (const float*)d_in[7];
    const float* bv   = (const float*)d_in[8];
    const float* Wrel = (const float*)d_in[9];
    const float* brel = (const float*)d_in[10];
    const float* Vb   = (const float*)d_in[11];
    const float* Wfc  = (const float*)d_in[12];
    const float* bfc  = (const float*)d_in[13];
    float* out = (float*)d_out;

    cudaFuncSetAttribute(relqk_kernel, cudaFuncAttributeMaxDynamicSharedMemorySize,
                         QK_SMEM_BYTES);
    cudaFuncSetAttribute(biasagg_kernel, cudaFuncAttributeMaxDynamicSharedMemorySize,
                         BA_BYTES);

    dim3 pg(32, 4, 4);
    proj_kernel<<<pg, 128>>>(q, k, v, Wq, bq, Wk, bk, Wv, bv, Vb);

    relqk_kernel<<<512, 256, QK_SMEM_BYTES>>>(Wrel, brel);

    dim3 sg(32, 8);
    softmax_kernel<<<sg, 256>>>();

    dim3 bag(32, 2, 4);
    biasagg_kernel<<<bag, 256, BA_BYTES>>>();

    dim3 fg(64, 2);
    fc_kernel<<<fg, 256>>>(Wfc, bfc, out);
}

// round 7
// speedup vs baseline: 1.1745x; 1.0656x over previous
#include <cuda_runtime.h>

typedef unsigned long long u64;

// ---------------- f32x2 packed-math helpers (sm_103a) ----------------
__device__ __forceinline__ u64 fma2(u64 a, u64 b, u64 c) {
    u64 d;
    asm("fma.rn.f32x2 %0, %1, %2, %3;" : "=l"(d) : "l"(a), "l"(b), "l"(c));
    return d;
}
__device__ __forceinline__ u64 add2(u64 a, u64 b) {
    u64 d;
    asm("add.rn.f32x2 %0, %1, %2;" : "=l"(d) : "l"(a), "l"(b));
    return d;
}
__device__ __forceinline__ u64 pack2(float lo, float hi) {
    u64 d;
    asm("mov.b64 %0, {%1, %2};" : "=l"(d) : "f"(lo), "f"(hi));
    return d;
}
__device__ __forceinline__ float2 unpack2(u64 v) {
    float2 r;
    asm("mov.b64 {%0, %1}, %2;" : "=f"(r.x), "=f"(r.y) : "l"(v));
    return r;
}

// Scratch (zero-initialized device globals)
__device__ float g_qproj[4 * 256 * 1024];   // [n][c][pix] (unscaled, for rel)
__device__ float g_qT[8 * 1024 * 128];      // [ng][pix][c], scaled by 1/T
__device__ float g_kT[8 * 1024 * 128];
__device__ float g_vT[8 * 1024 * 128];
__device__ float g_VbT[2 * 225 * 128];      // [g][w][c]
__device__ float g_agg[1024 * 4 * 256];     // attn . V
__device__ float g_aggb[1024 * 4 * 256];    // attn . V_bias
__device__ float g_logits[8 * 225 * 1024];  // [ng][wpos][pix]  rel / then attn
__device__ float g_qk[8 * 225 * 1024];      // [ng][wpos][pix]  raw qk dots

// ---------------------------------------------------------------------------
// proj: Y = W.X + b ; writes qT/kT/vT (transposed, q scaled) + qproj.
// z = 3 slice transposes V_bias. 128 threads, tile 64d x 128m, micro 8x8.
// ---------------------------------------------------------------------------
__global__ void __launch_bounds__(128) proj_kernel(
        const float* __restrict__ q, const float* __restrict__ k,
        const float* __restrict__ v,
        const float* __restrict__ Wq, const float* __restrict__ bq,
        const float* __restrict__ Wk, const float* __restrict__ bk,
        const float* __restrict__ Wv, const float* __restrict__ bv,
        const float* __restrict__ Vb) {
    __shared__ float w_s[32 * 68];    // [kk][d]
    __shared__ float x_s[32 * 128];   // [kk][m]

    const int p   = blockIdx.z;
    const int tid = threadIdx.x;

    if (p == 3) {   // V_bias transpose: [g][c][w] -> [g][w][c]
        int idx = (blockIdx.x * 4 + blockIdx.y) * 128 + tid;
        for (int i = idx; i < 57600; i += 16384) {
            int g = i / 28800, r = i - g * 28800;
            int w = r >> 7, c = r & 127;
            g_VbT[g * 28800 + r] = Vb[g * 28800 + c * 225 + w];
        }
        return;
    }

    const int m0 = blockIdx.x * 128;
    const int d0 = blockIdx.y * 64;
    const int n  = m0 >> 10;
    const int hw0 = m0 & 1023;

    const float *X, *Wm, *B;
    if (p == 0)      { X = q; Wm = Wq; B = bq; }
    else if (p == 1) { X = k; Wm = Wk; B = bk; }
    else             { X = v; Wm = Wv; B = bv; }

    const int td = tid >> 4;   // 0..7 -> d rows td*8..+7
    const int tm = tid & 15;   // m cols 2tm+32mq

    u64 acc[8][4];
    #pragma unroll
    for (int dd = 0; dd < 8; dd++) {
        float b = B[d0 + td * 8 + dd];
        u64 bb = pack2(b, b);
        #pragma unroll
        for (int mq = 0; mq < 4; mq++) acc[dd][mq] = bb;
    }

    const int dl   = tid >> 1;
    const int half = tid & 1;

    for (int kb = 0; kb < 8; kb++) {
        const int k0 = kb * 32;
        {
            const float* src = Wm + (d0 + dl) * 256 + k0 + half * 16;
            #pragma unroll
            for (int qq = 0; qq < 4; qq++) {
                float4 f = *(const float4*)(src + qq * 4);
                int kk = half * 16 + qq * 4;
                w_s[(kk + 0) * 68 + dl] = f.x;
                w_s[(kk + 1) * 68 + dl] = f.y;
                w_s[(kk + 2) * 68 + dl] = f.z;
                w_s[(kk + 3) * 68 + dl] = f.w;
            }
        }
        #pragma unroll
        for (int r = 0; r < 8; r++) {
            int idx = tid + r * 128;
            int kk = idx >> 5, m4 = idx & 31;
            *(float4*)(x_s + kk * 128 + m4 * 4) =
                *(const float4*)(X + (n * 256 + k0 + kk) * 1024 + hw0 + m4 * 4);
        }
        __syncthreads();

        #pragma unroll 8
        for (int kk = 0; kk < 32; kk++) {
            float4 wa = *(const float4*)(w_s + kk * 68 + td * 8);
            float4 wb = *(const float4*)(w_s + kk * 68 + td * 8 + 4);
            u64 xv[4];
            #pragma unroll
            for (int mq = 0; mq < 4; mq++)
                xv[mq] = *(const u64*)(x_s + kk * 128 + 2 * tm + 32 * mq);
            u64 wr[8];
            wr[0] = pack2(wa.x, wa.x); wr[1] = pack2(wa.y, wa.y);
            wr[2] = pack2(wa.z, wa.z); wr[3] = pack2(wa.w, wa.w);
            wr[4] = pack2(wb.x, wb.x); wr[5] = pack2(wb.y, wb.y);
            wr[6] = pack2(wb.z, wb.z); wr[7] = pack2(wb.w, wb.w);
            #pragma unroll
            for (int dd = 0; dd < 8; dd++)
                #pragma unroll
                for (int mq = 0; mq < 4; mq++)
                    acc[dd][mq] = fma2(wr[dd], xv[mq], acc[dd][mq]);
        }
        __syncthreads();
    }

    // transposed store -> [ng][pix][c]
    const int gg  = d0 >> 7;
    const int ng  = n * 2 + gg;
    const int ch0 = (d0 & 127) + td * 8;
    float* T = (p == 0) ? g_qT : (p == 1) ? g_kT : g_vT;
    const float s = (p == 0) ? 0.08838834764831845f : 1.f;
    #pragma unroll
    for (int mq = 0; mq < 4; mq++) {
        float2 t[8];
        #pragma unroll
        for (int dd = 0; dd < 8; dd++) t[dd] = unpack2(acc[dd][mq]);
        float* b0 = T + ng * 131072 + (hw0 + 2 * tm + 32 * mq) * 128 + ch0;
        *(float4*)(b0)       = make_float4(t[0].x*s, t[1].x*s, t[2].x*s, t[3].x*s);
        *(float4*)(b0 + 4)   = make_float4(t[4].x*s, t[5].x*s, t[6].x*s, t[7].x*s);
        *(float4*)(b0 + 128) = make_float4(t[0].y*s, t[1].y*s, t[2].y*s, t[3].y*s);
        *(float4*)(b0 + 132) = make_float4(t[4].y*s, t[5].y*s, t[6].y*s, t[7].y*s);
    }
    if (p == 0) {   // [c][pix] copy for rel GEMM
        #pragma unroll
        for (int dd = 0; dd < 8; dd++) {
            float* yp = g_qproj + (n * 256 + d0 + td * 8 + dd) * 1024 + hw0 + 2 * tm;
            #pragma unroll
            for (int mq = 0; mq < 4; mq++)
                *(float2*)(yp + 32 * mq) = unpack2(acc[dd][mq]);
        }
    }
}

// ---------------------------------------------------------------------------
// Fused rel-GEMM + QK kernel. bid < 256: rel -> g_logits (masked, +brel).
// bid >= 256: qk dots -> g_qk.
// ---------------------------------------------------------------------------
constexpr int QK_SMEM_FLOATS = 2 * 32 * 132 + 46 * 132;   // 14520
constexpr int QK_SMEM_BYTES  = QK_SMEM_FLOATS * 4;        // 58080

__device__ void rel_body(float* sm, int bid,
                         const float* __restrict__ Wrel,
                         const float* __restrict__ brel) {
    float* w_s = sm;            // 32*68
    float* x_s = sm + 2176;     // 32*128

    const int pix0 = (bid & 7) * 128;
    const int d0   = ((bid >> 3) & 3) * 64;
    const int ng   = bid >> 5;
    const int g    = ng & 1;
    const int tid  = threadIdx.x;

    const float* Wg = Wrel + g * 225 * 128;
    const float* X  = g_qproj + ng * 131072;

    const int td = tid >> 4;
    const int tm = tid & 15;

    u64 acc[4][4];
    #pragma unroll
    for (int dd = 0; dd < 4; dd++)
        #pragma unroll
        for (int mq = 0; mq < 4; mq++) acc[dd][mq] = 0ull;

    const int ldq = tid >> 3;
    const int lc4 = tid & 7;
    const int lk  = tid >> 5;
    const int lm4 = tid & 31;

    for (int kb = 0; kb < 4; kb++) {
        const int k0 = kb * 32;
        {
            float4 z = make_float4(0.f, 0.f, 0.f, 0.f);
            float4 fa = (d0 + ldq < 225)
                ? *(const float4*)(Wg + (d0 + ldq) * 128 + k0 + lc4 * 4) : z;
            float4 fb = (d0 + ldq + 32 < 225)
                ? *(const float4*)(Wg + (d0 + ldq + 32) * 128 + k0 + lc4 * 4) : z;
            w_s[(lc4 * 4 + 0) * 68 + ldq] = fa.x;
            w_s[(lc4 * 4 + 1) * 68 + ldq] = fa.y;
            w_s[(lc4 * 4 + 2) * 68 + ldq] = fa.z;
            w_s[(lc4 * 4 + 3) * 68 + ldq] = fa.w;
            w_s[(lc4 * 4 + 0) * 68 + ldq + 32] = fb.x;
            w_s[(lc4 * 4 + 1) * 68 + ldq + 32] = fb.y;
            w_s[(lc4 * 4 + 2) * 68 + ldq + 32] = fb.z;
            w_s[(lc4 * 4 + 3) * 68 + ldq + 32] = fb.w;
        }
        #pragma unroll
        for (int r = 0; r < 4; r++) {
            *(float4*)(x_s + (lk + 8 * r) * 128 + lm4 * 4) =
                *(const float4*)(X + (k0 + lk + 8 * r) * 1024 + pix0 + lm4 * 4);
        }
        __syncthreads();

        #pragma unroll 8
        for (int kk = 0; kk < 32; kk++) {
            float4 wv = *(const float4*)(w_s + kk * 68 + td * 4);
            u64 xv[4];
            #pragma unroll
            for (int mq = 0; mq < 4; mq++)
                xv[mq] = *(const u64*)(x_s + kk * 128 + 2 * tm + 32 * mq);
            u64 w0 = pack2(wv.x, wv.x), w1 = pack2(wv.y, wv.y);
            u64 w2 = pack2(wv.z, wv.z), w3 = pack2(wv.w, wv.w);
            #pragma unroll
            for (int mq = 0; mq < 4; mq++) {
                acc[0][mq] = fma2(w0, xv[mq], acc[0][mq]);
                acc[1][mq] = fma2(w1, xv[mq], acc[1][mq]);
                acc[2][mq] = fma2(w2, xv[mq], acc[2][mq]);
                acc[3][mq] = fma2(w3, xv[mq], acc[3][mq]);
            }
        }
        __syncthreads();
    }

    float* Lb = g_logits + ng * 230400;
    #pragma unroll
    for (int dd = 0; dd < 4; dd++) {
        const int wpos = d0 + td * 4 + dd;
        if (wpos >= 225) continue;
        const float bv = brel[g * 225 + wpos];
        const int dy = wpos / 15;
        const int dxw = wpos - dy * 15;
        #pragma unroll
        for (int mq = 0; mq < 4; mq++) {
            const int pix = pix0 + 2 * tm + 32 * mq;
            const int y = pix >> 5, x = pix & 31;
            const int iy = y + dy - 7;
            const bool ry = (iy >= 0) && (iy < 32);
            const int ix0 = x + dxw - 7;
            float2 t = unpack2(acc[dd][mq]);
            float v0 = (ry && ix0 >= 0 && ix0 < 32) ? t.x + bv : -1e8f;
            float v1 = (ry && ix0 + 1 >= 0 && ix0 + 1 < 32) ? t.y + bv : -1e8f;
            *(float2*)(Lb + wpos * 1024 + pix) = make_float2(v0, v1);
        }
    }
}

__device__ void qk_body(float* sm, int b) {
    float* q0s  = sm;
    float* q1s  = sm + 32 * 132;
    float* slab = sm + 2 * 32 * 132;

    const int yp = b & 15;
    const int y0 = yp * 2, y1 = y0 + 1;
    const int h  = (b >> 4) & 1;
    const int d0 = h ? 8 : 0;
    const int d1 = h ? 15 : 8;
    const int ng = b >> 5;
    const int tid = threadIdx.x;
    const int x = tid & 31, w = tid >> 5;

    const float* qT = g_qT + ng * 131072;
    const float* kT = g_kT + ng * 131072;
    float* Qb = g_qk + ng * 230400;

    for (int i = tid; i < 1024; i += 256) {
        int xx = i >> 5, c4 = i & 31;
        *(float4*)(q0s + xx * 132 + c4 * 4) =
            *(const float4*)(qT + (y0 * 32 + xx) * 128 + c4 * 4);
        *(float4*)(q1s + xx * 132 + c4 * 4) =
            *(const float4*)(qT + (y1 * 32 + xx) * 128 + c4 * 4);
    }
    for (int i = tid; i < 14 * 32; i += 256) {
        int e = i >> 5, c4 = i & 31;
        int px = (e < 7) ? e : e + 32;
        *(float4*)(slab + px * 132 + c4 * 4) = make_float4(0.f, 0.f, 0.f, 0.f);
    }

    const int dx0 = w;
    const int dx1 = (w < 7) ? w + 8 : 0;
    const int Rlo = y0 + d0 - 7;
    const int Rhi = y0 + d1 - 7;

    for (int R = Rlo; R <= Rhi; R++) {
        if (R < 0 || R > 31) continue;
        __syncthreads();
        for (int i = tid; i < 1024; i += 256) {
            int ix = i >> 5, c4 = i & 31;
            *(float4*)(slab + (ix + 7) * 132 + c4 * 4) =
                *(const float4*)(kT + (R * 32 + ix) * 128 + c4 * 4);
        }
        __syncthreads();

        u64 a00 = 0, a01 = 0, a10 = 0, a11 = 0;
        const float* qp0 = q0s + x * 132;
        const float* qp1 = q1s + x * 132;
        const float* k0p = slab + (x + dx0) * 132;
        const float* k1p = slab + (x + dx1) * 132;
        #pragma unroll 8
        for (int c4 = 0; c4 < 32; c4++) {
            ulonglong2 q0v = *(const ulonglong2*)(qp0 + 4 * c4);
            ulonglong2 q1v = *(const ulonglong2*)(qp1 + 4 * c4);
            ulonglong2 k0v = *(const ulonglong2*)(k0p + 4 * c4);
            ulonglong2 k1v = *(const ulonglong2*)(k1p + 4 * c4);
            a00 = fma2(q0v.x, k0v.x, a00); a00 = fma2(q0v.y, k0v.y, a00);
            a01 = fma2(q0v.x, k1v.x, a01); a01 = fma2(q0v.y, k1v.y, a01);
            a10 = fma2(q1v.x, k0v.x, a10); a10 = fma2(q1v.y, k0v.y, a10);
            a11 = fma2(q1v.x, k1v.x, a11); a11 = fma2(q1v.y, k1v.y, a11);
        }

        const int dyA = R - y0 + 7;
        const int dyB = dyA - 1;
        if (dyA >= d0 && dyA < d1) {
            float2 t = unpack2(a00);
            Qb[(dyA * 15 + dx0) * 1024 + y0 * 32 + x] = t.x + t.y;
            if (w < 7) {
                float2 u = unpack2(a01);
                Qb[(dyA * 15 + dx1) * 1024 + y0 * 32 + x] = u.x + u.y;
            }
        }
        if (dyB >= d0 && dyB < d1) {
            float2 t = unpack2(a10);
            Qb[(dyB * 15 + dx0) * 1024 + y1 * 32 + x] = t.x + t.y;
            if (w < 7) {
                float2 u = unpack2(a11);
                Qb[(dyB * 15 + dx1) * 1024 + y1 * 32 + x] = u.x + u.y;
            }
        }
    }
}

__global__ void __launch_bounds__(256) relqk_kernel(
        const float* __restrict__ Wrel, const float* __restrict__ brel) {
    extern __shared__ float sm[];
    const int bid = blockIdx.x;
    if (bid < 256) rel_body(sm, bid, Wrel, brel);
    else           qk_body(sm, bid - 256);
}

// ---------------------------------------------------------------------------
// Softmax: attn = softmax_w(g_logits + g_qk), written back to g_logits.
// ---------------------------------------------------------------------------
__global__ void __launch_bounds__(256) softmax_kernel() {
    __shared__ float att[7200];
    __shared__ float red[256];
    const int y = blockIdx.x, ng = blockIdx.y;
    const int tid = threadIdx.x;
    const int x = tid & 31, w = tid >> 5;
    float* L = g_logits + ng * 230400;
    const float* Q = g_qk + ng * 230400;

    for (int i = tid; i < 1800; i += 256) {
        int ww = i >> 3, x4 = i & 7;
        float4 a = *(const float4*)(L + ww * 1024 + y * 32 + x4 * 4);
        float4 b = *(const float4*)(Q + ww * 1024 + y * 32 + x4 * 4);
        *(float4*)(att + ww * 32 + x4 * 4) =
            make_float4(a.x + b.x, a.y + b.y, a.z + b.z, a.w + b.w);
    }
    __syncthreads();

    float lm = -1e30f;
    for (int ww = w; ww < 225; ww += 8) lm = fmaxf(lm, att[ww * 32 + x]);
    red[w * 32 + x] = lm;
    __syncthreads();
    float m = red[x];
    #pragma unroll
    for (int i = 1; i < 8; i++) m = fmaxf(m, red[i * 32 + x]);
    __syncthreads();
    float ls = 0.f;
    for (int ww = w; ww < 225; ww += 8) {
        float e = __expf(att[ww * 32 + x] - m);
        att[ww * 32 + x] = e;
        ls += e;
    }
    red[w * 32 + x] = ls;
    __syncthreads();
    float s = red[x];
    #pragma unroll
    for (int i = 1; i < 8; i++) s += red[i * 32 + x];
    float rinv = 1.f / s;
    for (int ww = w; ww < 225; ww += 8) att[ww * 32 + x] *= rinv;
    __syncthreads();

    for (int i = tid; i < 1800; i += 256) {
        int ww = i >> 3, x4 = i & 7;
        *(float4*)(L + ww * 1024 + y * 32 + x4 * 4) =
            *(const float4*)(att + ww * 32 + x4 * 4);
    }
}

// ---------------------------------------------------------------------------
// Fused agg + bias launch.
//  bid < 128 : bias GEMM  g_aggb = attn . VbT   (64 pix x 128 c tile, K=225)
//  bid >= 128: V agg      g_agg  = attn . V_unfold (per y row)
// ---------------------------------------------------------------------------
constexpr int AGG_ATT  = 0;                 // [225][32]
constexpr int AGG_RED  = 7200;
constexpr int AGG_SLAB = 7456;              // [46][132]
constexpr int AGG_FLOATS = 7456 + 46 * 132; // 13528
constexpr int AGG_BYTES  = AGG_FLOATS * 4;  // 54112

__device__ void bias_body(float* sm, int b) {
    float* a_s = sm;            // 32*72
    float* b_s = sm + 2304;     // 32*128

    const int pix0 = (b & 15) * 64;
    const int ng   = b >> 4;
    const int g    = ng & 1, n = ng >> 1;
    const int tid  = threadIdx.x;

    const float* attn = g_logits + ng * 230400;
    const float* vbt  = g_VbT + g * 28800;

    const int td = tid >> 4;
    const int tm = tid & 15;

    u64 acc[4][4];
    #pragma unroll
    for (int dd = 0; dd < 4; dd++)
        #pragma unroll
        for (int mq = 0; mq < 4; mq++) acc[dd][mq] = 0ull;

    const float4 z4 = make_float4(0.f, 0.f, 0.f, 0.f);

    for (int kb = 0; kb < 8; kb++) {
        const int k0 = kb * 32;
        #pragma unroll
        for (int r = 0; r < 2; r++) {
            int idx = tid + r * 256;
            int kk = idx >> 4, p4 = idx & 15;
            int w = k0 + kk;
            float4 v = (w < 225)
                ? *(const float4*)(attn + w * 1024 + pix0 + p4 * 4) : z4;
            *(float4*)(a_s + kk * 72 + p4 * 4) = v;
        }
        #pragma unroll
        for (int r = 0; r < 4; r++) {
            int idx = tid + r * 256;
            int kk = idx >> 5, c4 = idx & 31;
            int w = k0 + kk;
            float4 v = (w < 225)
                ? *(const float4*)(vbt + w * 128 + c4 * 4) : z4;
            *(float4*)(b_s + kk * 128 + c4 * 4) = v;
        }
        __syncthreads();

        #pragma unroll 8
        for (int kk = 0; kk < 32; kk++) {
            float4 av = *(const float4*)(a_s + kk * 72 + td * 4);
            u64 xv[4];
            #pragma unroll
            for (int mq = 0; mq < 4; mq++)
                xv[mq] = *(const u64*)(b_s + kk * 128 + 2 * tm + 32 * mq);
            u64 w0 = pack2(av.x, av.x), w1 = pack2(av.y, av.y);
            u64 w2 = pack2(av.z, av.z), w3 = pack2(av.w, av.w);
            #pragma unroll
            for (int mq = 0; mq < 4; mq++) {
                acc[0][mq] = fma2(w0, xv[mq], acc[0][mq]);
                acc[1][mq] = fma2(w1, xv[mq], acc[1][mq]);
                acc[2][mq] = fma2(w2, xv[mq], acc[2][mq]);
                acc[3][mq] = fma2(w3, xv[mq], acc[3][mq]);
            }
        }
        __syncthreads();
    }

    #pragma unroll
    for (int dd = 0; dd < 4; dd++) {
        const int pix = pix0 + td * 4 + dd;
        float* ap = g_aggb + (pix * 4 + n) * 256 + g * 128 + 2 * tm;
        #pragma unroll
        for (int mq = 0; mq < 4; mq++)
            *(float2*)(ap + 32 * mq) = unpack2(acc[dd][mq]);
    }
}

__device__ void agg_body(float* sm, int b) {
    float* att  = sm + AGG_ATT;
    float* slab = sm + AGG_SLAB;

    const int y = b & 31;
    const int rest = b >> 5;
    const int g = rest & 1, n = rest >> 1;
    const int ng = n * 2 + g;
    const int tid = threadIdx.x;
    const int x = tid & 31, w = tid >> 5;
    const int cbase = w * 16;

    const float* vT = g_vT + ng * 131072;
    const float* Lb = g_logits + ng * 230400;

    for (int i = tid; i < 1800; i += 256) {
        int ww = i >> 3, x4 = i & 7;
        *(float4*)(att + ww * 32 + x4 * 4) =
            *(const float4*)(Lb + ww * 1024 + y * 32 + x4 * 4);
    }
    for (int i = tid; i < 14 * 32; i += 256) {
        int e = i >> 5, c4 = i & 31;
        int px = (e < 7) ? e : e + 32;
        *(float4*)(slab + px * 132 + c4 * 4) = make_float4(0.f, 0.f, 0.f, 0.f);
    }

    u64 acc[8];
    #pragma unroll
    for (int j = 0; j < 8; j++) acc[j] = 0;

    for (int dy = 0; dy < 15; dy++) {
        const int iy = y + dy - 7;
        if (iy < 0 || iy >= 32) continue;      // attn exactly 0 on this row
        __syncthreads();
        for (int i = tid; i < 1024; i += 256) {
            int ix = i >> 5, c4 = i & 31;
            *(float4*)(slab + (ix + 7) * 132 + c4 * 4) =
                *(const float4*)(vT + (iy * 32 + ix) * 128 + c4 * 4);
        }
        __syncthreads();

        const float* awrow = att + dy * 15 * 32 + x;
        #pragma unroll 5
        for (int dx = 0; dx < 15; dx++) {
            float aw = awrow[dx * 32];
            u64 aw2 = pack2(aw, aw);
            const float* vp = slab + (x + dx) * 132 + cbase;
            #pragma unroll
            for (int j = 0; j < 4; j++) {
                ulonglong2 vv = *(const ulonglong2*)(vp + 4 * j);
                acc[2 * j]     = fma2(aw2, vv.x, acc[2 * j]);
                acc[2 * j + 1] = fma2(aw2, vv.y, acc[2 * j + 1]);
            }
        }
    }

    float* ap = g_agg + ((y * 32 + x) * 4 + n) * 256 + g * 128 + cbase;
    #pragma unroll
    for (int j = 0; j < 8; j++) *(float2*)(ap + 2 * j) = unpack2(acc[j]);
}

__global__ void __launch_bounds__(256) aggbias_kernel() {
    extern __shared__ float sm[];
    const int bid = blockIdx.x;
    if (bid < 128) bias_body(sm, bid);
    else           agg_body(sm, bid - 128);
}

// ---------------------------------------------------------------------------
// Output FC: out[r, d] = sum_c (agg+aggb)[r, c] * Wfc[d, c] + bfc[d]
// ---------------------------------------------------------------------------
__global__ void __launch_bounds__(256) fc_kernel(
        const float* __restrict__ Wfc, const float* __restrict__ bfc,
        float* __restrict__ out) {
    __shared__ float w_s[32 * 68];
    __shared__ float x_s[32 * 128];

    const int r0 = blockIdx.x * 64;
    const int d0 = blockIdx.y * 128;
    const int tid = threadIdx.x;
    const int td = tid >> 4;
    const int tm = tid & 15;

    u64 acc[4][4];
    #pragma unroll
    for (int mq = 0; mq < 4; mq++) {
        int d = d0 + 2 * tm + 32 * mq;
        u64 bb = pack2(bfc[d], bfc[d + 1]);
        #pragma unroll
        for (int rr = 0; rr < 4; rr++) acc[rr][mq] = bb;
    }

    const int lrq = tid >> 3;
    const int lc4 = tid & 7;
    const int ld  = tid & 127;
    const int lch = tid >> 7;

    for (int kb = 0; kb < 8; kb++) {
        const int k0 = kb * 32;
        {
            const int i1 = (r0 + lrq) * 256 + k0 + lc4 * 4;
            const int i2 = (r0 + lrq + 32) * 256 + k0 + lc4 * 4;
            float4 fa = *(const float4*)(g_agg + i1);
            float4 ba = *(const float4*)(g_aggb + i1);
            float4 fb = *(const float4*)(g_agg + i2);
            float4 bb = *(const float4*)(g_aggb + i2);
            fa.x += ba.x; fa.y += ba.y; fa.z += ba.z; fa.w += ba.w;
            fb.x += bb.x; fb.y += bb.y; fb.z += bb.z; fb.w += bb.w;
            w_s[(lc4 * 4 + 0) * 68 + lrq] = fa.x;
            w_s[(lc4 * 4 + 1) * 68 + lrq] = fa.y;
            w_s[(lc4 * 4 + 2) * 68 + lrq] = fa.z;
            w_s[(lc4 * 4 + 3) * 68 + lrq] = fa.w;
            w_s[(lc4 * 4 + 0) * 68 + lrq + 32] = fb.x;
            w_s[(lc4 * 4 + 1) * 68 + lrq + 32] = fb.y;
            w_s[(lc4 * 4 + 2) * 68 + lrq + 32] = fb.z;
            w_s[(lc4 * 4 + 3) * 68 + lrq + 32] = fb.w;
        }
        #pragma unroll
        for (int i = 0; i < 4; i++) {
            int cq = lch * 4 + i;
            float4 f = *(const float4*)(Wfc + (d0 + ld) * 256 + k0 + cq * 4);
            x_s[(cq * 4 + 0) * 128 + ld] = f.x;
            x_s[(cq * 4 + 1) * 128 + ld] = f.y;
            x_s[(cq * 4 + 2) * 128 + ld] = f.z;
            x_s[(cq * 4 + 3) * 128 + ld] = f.w;
        }
        __syncthreads();

        #pragma unroll 8
        for (int kk = 0; kk < 32; kk++) {
            float4 wv = *(const float4*)(w_s + kk * 68 + td * 4);
            u64 xv[4];
            #pragma unroll
            for (int mq = 0; mq < 4; mq++)
                xv[mq] = *(const u64*)(x_s + kk * 128 + 2 * tm + 32 * mq);
            u64 w0 = pack2(wv.x, wv.x), w1 = pack2(wv.y, wv.y);
            u64 w2 = pack2(wv.z, wv.z), w3 = pack2(wv.w, wv.w);
            #pragma unroll
            for (int mq = 0; mq < 4; mq++) {
                acc[0][mq] = fma2(w0, xv[mq], acc[0][mq]);
                acc[1][mq] = fma2(w1, xv[mq], acc[1][mq]);
                acc[2][mq] = fma2(w2, xv[mq], acc[2][mq]);
                acc[3][mq] = fma2(w3, xv[mq], acc[3][mq]);
            }
        }
        __syncthreads();
    }

    #pragma unroll
    for (int rr = 0; rr < 4; rr++) {
        float* op = out + (r0 + td * 4 + rr) * 256 + d0 + 2 * tm;
        #pragma unroll
        for (int mq = 0; mq < 4; mq++)
            *(float2*)(op + 32 * mq) = unpack2(acc[rr][mq]);
    }
}

// ---------------------------------------------------------------------------
extern "C" void kernel_launch(void* const* d_in, const int* in_sizes, int n_in,
                              void* d_out, int out_size) {
    const float* q    = (const float*)d_in[0];
    const float* k    = (const float*)d_in[1];
    const float* v    = (const float*)d_in[2];
    const float* Wq   = (const float*)d_in[3];
    const float* bq   = (const float*)d_in[4];
    const float* Wk   = (const float*)d_in[5];
    const float* bk   = (const float*)d_in[6];
    const float* Wv   = (const float*)d_in[7];
    const float* bv   = (const float*)d_in[8];
    const float* Wrel = (const float*)d_in[9];
    const float* brel = (const float*)d_in[10];
    const float* Vb   = (const float*)d_in[11];
    const float* Wfc  = (const float*)d_in[12];
    const float* bfc  = (const float*)d_in[13];
    float* out = (float*)d_out;

    cudaFuncSetAttribute(relqk_kernel, cudaFuncAttributeMaxDynamicSharedMemorySize,
                         QK_SMEM_BYTES);
    cudaFuncSetAttribute(aggbias_kernel, cudaFuncAttributeMaxDynamicSharedMemorySize,
                         AGG_BYTES);

    dim3 pg(32, 4, 4);
    proj_kernel<<<pg, 128>>>(q, k, v, Wq, bq, Wk, bk, Wv, bv, Vb);

    relqk_kernel<<<512, 256, QK_SMEM_BYTES>>>(Wrel, brel);

    dim3 sg(32, 8);
    softmax_kernel<<<sg, 256>>>();

    aggbias_kernel<<<384, 256, AGG_BYTES>>>();

    dim3 fg(64, 2);
    fc_kernel<<<fg, 256>>>(Wfc, bfc, out);
}

// round 8
// speedup vs baseline: 1.2001x; 1.0218x over previous
#include <cuda_runtime.h>

typedef unsigned long long u64;

// ---------------- f32x2 packed-math helpers (sm_103a) ----------------
__device__ __forceinline__ u64 fma2(u64 a, u64 b, u64 c) {
    u64 d;
    asm("fma.rn.f32x2 %0, %1, %2, %3;" : "=l"(d) : "l"(a), "l"(b), "l"(c));
    return d;
}
__device__ __forceinline__ u64 add2(u64 a, u64 b) {
    u64 d;
    asm("add.rn.f32x2 %0, %1, %2;" : "=l"(d) : "l"(a), "l"(b));
    return d;
}
__device__ __forceinline__ u64 pack2(float lo, float hi) {
    u64 d;
    asm("mov.b64 %0, {%1, %2};" : "=l"(d) : "f"(lo), "f"(hi));
    return d;
}
__device__ __forceinline__ float2 unpack2(u64 v) {
    float2 r;
    asm("mov.b64 {%0, %1}, %2;" : "=f"(r.x), "=f"(r.y) : "l"(v));
    return r;
}

// Scratch (zero-initialized device globals)
__device__ float g_qproj[4 * 256 * 1024];   // [n][c][pix] (unscaled, for rel)
__device__ float g_qT[8 * 1024 * 128];      // [ng][pix][c], scaled by 1/T
__device__ float g_kT[8 * 1024 * 128];
__device__ float g_vT[8 * 1024 * 128];
__device__ float g_VbT[2 * 225 * 128];      // [g][w][c]
__device__ float g_agg[1024 * 4 * 256];     // attn . V
__device__ float g_aggb[1024 * 4 * 256];    // attn . V_bias
__device__ float g_logits[8 * 225 * 1024];  // [ng][wpos][pix]  rel / then attn
__device__ float g_qk[8 * 225 * 1024];      // [ng][wpos][pix]  raw qk dots

// ---------------------------------------------------------------------------
// proj: Y = W.X + b ; writes qT/kT/vT (transposed, q scaled) + qproj.
// z = 3 slice transposes V_bias. 128 threads, tile 64d x 128m, micro 8x8.
// ---------------------------------------------------------------------------
__global__ void __launch_bounds__(128) proj_kernel(
        const float* __restrict__ q, const float* __restrict__ k,
        const float* __restrict__ v,
        const float* __restrict__ Wq, const float* __restrict__ bq,
        const float* __restrict__ Wk, const float* __restrict__ bk,
        const float* __restrict__ Wv, const float* __restrict__ bv,
        const float* __restrict__ Vb) {
    __shared__ float w_s[32 * 68];    // [kk][d]
    __shared__ float x_s[32 * 128];   // [kk][m]

    const int p   = blockIdx.z;
    const int tid = threadIdx.x;

    if (p == 3) {   // V_bias transpose: [g][c][w] -> [g][w][c]
        int idx = (blockIdx.x * 4 + blockIdx.y) * 128 + tid;
        for (int i = idx; i < 57600; i += 16384) {
            int g = i / 28800, r = i - g * 28800;
            int w = r >> 7, c = r & 127;
            g_VbT[g * 28800 + r] = Vb[g * 28800 + c * 225 + w];
        }
        return;
    }

    const int m0 = blockIdx.x * 128;
    const int d0 = blockIdx.y * 64;
    const int n  = m0 >> 10;
    const int hw0 = m0 & 1023;

    const float *X, *Wm, *B;
    if (p == 0)      { X = q; Wm = Wq; B = bq; }
    else if (p == 1) { X = k; Wm = Wk; B = bk; }
    else             { X = v; Wm = Wv; B = bv; }

    const int td = tid >> 4;   // 0..7 -> d rows td*8..+7
    const int tm = tid & 15;   // m cols 2tm+32mq

    u64 acc[8][4];
    #pragma unroll
    for (int dd = 0; dd < 8; dd++) {
        float b = B[d0 + td * 8 + dd];
        u64 bb = pack2(b, b);
        #pragma unroll
        for (int mq = 0; mq < 4; mq++) acc[dd][mq] = bb;
    }

    const int dl   = tid >> 1;
    const int half = tid & 1;

    for (int kb = 0; kb < 8; kb++) {
        const int k0 = kb * 32;
        {
            const float* src = Wm + (d0 + dl) * 256 + k0 + half * 16;
            #pragma unroll
            for (int qq = 0; qq < 4; qq++) {
                float4 f = *(const float4*)(src + qq * 4);
                int kk = half * 16 + qq * 4;
                w_s[(kk + 0) * 68 + dl] = f.x;
                w_s[(kk + 1) * 68 + dl] = f.y;
                w_s[(kk + 2) * 68 + dl] = f.z;
                w_s[(kk + 3) * 68 + dl] = f.w;
            }
        }
        #pragma unroll
        for (int r = 0; r < 8; r++) {
            int idx = tid + r * 128;
            int kk = idx >> 5, m4 = idx & 31;
            *(float4*)(x_s + kk * 128 + m4 * 4) =
                *(const float4*)(X + (n * 256 + k0 + kk) * 1024 + hw0 + m4 * 4);
        }
        __syncthreads();

        #pragma unroll 8
        for (int kk = 0; kk < 32; kk++) {
            float4 wa = *(const float4*)(w_s + kk * 68 + td * 8);
            float4 wb = *(const float4*)(w_s + kk * 68 + td * 8 + 4);
            u64 xv[4];
            #pragma unroll
            for (int mq = 0; mq < 4; mq++)
                xv[mq] = *(const u64*)(x_s + kk * 128 + 2 * tm + 32 * mq);
            u64 wr[8];
            wr[0] = pack2(wa.x, wa.x); wr[1] = pack2(wa.y, wa.y);
            wr[2] = pack2(wa.z, wa.z); wr[3] = pack2(wa.w, wa.w);
            wr[4] = pack2(wb.x, wb.x); wr[5] = pack2(wb.y, wb.y);
            wr[6] = pack2(wb.z, wb.z); wr[7] = pack2(wb.w, wb.w);
            #pragma unroll
            for (int dd = 0; dd < 8; dd++)
                #pragma unroll
                for (int mq = 0; mq < 4; mq++)
                    acc[dd][mq] = fma2(wr[dd], xv[mq], acc[dd][mq]);
        }
        __syncthreads();
    }

    // transposed store -> [ng][pix][c]
    const int gg  = d0 >> 7;
    const int ng  = n * 2 + gg;
    const int ch0 = (d0 & 127) + td * 8;
    float* T = (p == 0) ? g_qT : (p == 1) ? g_kT : g_vT;
    const float s = (p == 0) ? 0.08838834764831845f : 1.f;
    #pragma unroll
    for (int mq = 0; mq < 4; mq++) {
        float2 t[8];
        #pragma unroll
        for (int dd = 0; dd < 8; dd++) t[dd] = unpack2(acc[dd][mq]);
        float* b0 = T + ng * 131072 + (hw0 + 2 * tm + 32 * mq) * 128 + ch0;
        *(float4*)(b0)       = make_float4(t[0].x*s, t[1].x*s, t[2].x*s, t[3].x*s);
        *(float4*)(b0 + 4)   = make_float4(t[4].x*s, t[5].x*s, t[6].x*s, t[7].x*s);
        *(float4*)(b0 + 128) = make_float4(t[0].y*s, t[1].y*s, t[2].y*s, t[3].y*s);
        *(float4*)(b0 + 132) = make_float4(t[4].y*s, t[5].y*s, t[6].y*s, t[7].y*s);
    }
    if (p == 0) {   // [c][pix] copy for rel GEMM
        #pragma unroll
        for (int dd = 0; dd < 8; dd++) {
            float* yp = g_qproj + (n * 256 + d0 + td * 8 + dd) * 1024 + hw0 + 2 * tm;
            #pragma unroll
            for (int mq = 0; mq < 4; mq++)
                *(float2*)(yp + 32 * mq) = unpack2(acc[dd][mq]);
        }
    }
}

// ---------------------------------------------------------------------------
// Fused rel-GEMM + QK kernel. bid < 256: rel -> g_logits (masked, +brel).
// bid >= 256: qk dots -> g_qk.
// ---------------------------------------------------------------------------
constexpr int QK_SMEM_FLOATS = 2 * 32 * 132 + 46 * 132;   // 14520
constexpr int QK_SMEM_BYTES  = QK_SMEM_FLOATS * 4;        // 58080

__device__ void rel_body(float* sm, int bid,
                         const float* __restrict__ Wrel,
                         const float* __restrict__ brel) {
    float* w_s = sm;            // 32*68
    float* x_s = sm + 2176;     // 32*128

    const int pix0 = (bid & 7) * 128;
    const int d0   = ((bid >> 3) & 3) * 64;
    const int ng   = bid >> 5;
    const int g    = ng & 1;
    const int tid  = threadIdx.x;

    const float* Wg = Wrel + g * 225 * 128;
    const float* X  = g_qproj + ng * 131072;

    const int td = tid >> 4;
    const int tm = tid & 15;

    u64 acc[4][4];
    #pragma unroll
    for (int dd = 0; dd < 4; dd++)
        #pragma unroll
        for (int mq = 0; mq < 4; mq++) acc[dd][mq] = 0ull;

    const int ldq = tid >> 3;
    const int lc4 = tid & 7;
    const int lk  = tid >> 5;
    const int lm4 = tid & 31;

    for (int kb = 0; kb < 4; kb++) {
        const int k0 = kb * 32;
        {
            float4 z = make_float4(0.f, 0.f, 0.f, 0.f);
            float4 fa = (d0 + ldq < 225)
                ? *(const float4*)(Wg + (d0 + ldq) * 128 + k0 + lc4 * 4) : z;
            float4 fb = (d0 + ldq + 32 < 225)
                ? *(const float4*)(Wg + (d0 + ldq + 32) * 128 + k0 + lc4 * 4) : z;
            w_s[(lc4 * 4 + 0) * 68 + ldq] = fa.x;
            w_s[(lc4 * 4 + 1) * 68 + ldq] = fa.y;
            w_s[(lc4 * 4 + 2) * 68 + ldq] = fa.z;
            w_s[(lc4 * 4 + 3) * 68 + ldq] = fa.w;
            w_s[(lc4 * 4 + 0) * 68 + ldq + 32] = fb.x;
            w_s[(lc4 * 4 + 1) * 68 + ldq + 32] = fb.y;
            w_s[(lc4 * 4 + 2) * 68 + ldq + 32] = fb.z;
            w_s[(lc4 * 4 + 3) * 68 + ldq + 32] = fb.w;
        }
        #pragma unroll
        for (int r = 0; r < 4; r++) {
            *(float4*)(x_s + (lk + 8 * r) * 128 + lm4 * 4) =
                *(const float4*)(X + (k0 + lk + 8 * r) * 1024 + pix0 + lm4 * 4);
        }
        __syncthreads();

        #pragma unroll 8
        for (int kk = 0; kk < 32; kk++) {
            float4 wv = *(const float4*)(w_s + kk * 68 + td * 4);
            u64 xv[4];
            #pragma unroll
            for (int mq = 0; mq < 4; mq++)
                xv[mq] = *(const u64*)(x_s + kk * 128 + 2 * tm + 32 * mq);
            u64 w0 = pack2(wv.x, wv.x), w1 = pack2(wv.y, wv.y);
            u64 w2 = pack2(wv.z, wv.z), w3 = pack2(wv.w, wv.w);
            #pragma unroll
            for (int mq = 0; mq < 4; mq++) {
                acc[0][mq] = fma2(w0, xv[mq], acc[0][mq]);
                acc[1][mq] = fma2(w1, xv[mq], acc[1][mq]);
                acc[2][mq] = fma2(w2, xv[mq], acc[2][mq]);
                acc[3][mq] = fma2(w3, xv[mq], acc[3][mq]);
            }
        }
        __syncthreads();
    }

    float* Lb = g_logits + ng * 230400;
    #pragma unroll
    for (int dd = 0; dd < 4; dd++) {
        const int wpos = d0 + td * 4 + dd;
        if (wpos >= 225) continue;
        const float bv = brel[g * 225 + wpos];
        const int dy = wpos / 15;
        const int dxw = wpos - dy * 15;
        #pragma unroll
        for (int mq = 0; mq < 4; mq++) {
            const int pix = pix0 + 2 * tm + 32 * mq;
            const int y = pix >> 5, x = pix & 31;
            const int iy = y + dy - 7;
            const bool ry = (iy >= 0) && (iy < 32);
            const int ix0 = x + dxw - 7;
            float2 t = unpack2(acc[dd][mq]);
            float v0 = (ry && ix0 >= 0 && ix0 < 32) ? t.x + bv : -1e8f;
            float v1 = (ry && ix0 + 1 >= 0 && ix0 + 1 < 32) ? t.y + bv : -1e8f;
            *(float2*)(Lb + wpos * 1024 + pix) = make_float2(v0, v1);
        }
    }
}

__device__ void qk_body(float* sm, int b) {
    float* q0s  = sm;
    float* q1s  = sm + 32 * 132;
    float* slab = sm + 2 * 32 * 132;

    const int yp = b & 15;
    const int y0 = yp * 2, y1 = y0 + 1;
    const int h  = (b >> 4) & 1;
    const int d0 = h ? 8 : 0;
    const int d1 = h ? 15 : 8;
    const int ng = b >> 5;
    const int tid = threadIdx.x;
    const int x = tid & 31, w = tid >> 5;

    const float* qT = g_qT + ng * 131072;
    const float* kT = g_kT + ng * 131072;
    float* Qb = g_qk + ng * 230400;

    for (int i = tid; i < 1024; i += 256) {
        int xx = i >> 5, c4 = i & 31;
        *(float4*)(q0s + xx * 132 + c4 * 4) =
            *(const float4*)(qT + (y0 * 32 + xx) * 128 + c4 * 4);
        *(float4*)(q1s + xx * 132 + c4 * 4) =
            *(const float4*)(qT + (y1 * 32 + xx) * 128 + c4 * 4);
    }
    for (int i = tid; i < 14 * 32; i += 256) {
        int e = i >> 5, c4 = i & 31;
        int px = (e < 7) ? e : e + 32;
        *(float4*)(slab + px * 132 + c4 * 4) = make_float4(0.f, 0.f, 0.f, 0.f);
    }

    const int dx0 = w;
    const int dx1 = (w < 7) ? w + 8 : 0;
    const int Rlo = y0 + d0 - 7;
    const int Rhi = y0 + d1 - 7;

    for (int R = Rlo; R <= Rhi; R++) {
        if (R < 0 || R > 31) continue;
        __syncthreads();
        for (int i = tid; i < 1024; i += 256) {
            int ix = i >> 5, c4 = i & 31;
            *(float4*)(slab + (ix + 7) * 132 + c4 * 4) =
                *(const float4*)(kT + (R * 32 + ix) * 128 + c4 * 4);
        }
        __syncthreads();

        u64 a00 = 0, a01 = 0, a10 = 0, a11 = 0;
        const float* qp0 = q0s + x * 132;
        const float* qp1 = q1s + x * 132;
        const float* k0p = slab + (x + dx0) * 132;
        const float* k1p = slab + (x + dx1) * 132;
        #pragma unroll 8
        for (int c4 = 0; c4 < 32; c4++) {
            ulonglong2 q0v = *(const ulonglong2*)(qp0 + 4 * c4);
            ulonglong2 q1v = *(const ulonglong2*)(qp1 + 4 * c4);
            ulonglong2 k0v = *(const ulonglong2*)(k0p + 4 * c4);
            ulonglong2 k1v = *(const ulonglong2*)(k1p + 4 * c4);
            a00 = fma2(q0v.x, k0v.x, a00); a00 = fma2(q0v.y, k0v.y, a00);
            a01 = fma2(q0v.x, k1v.x, a01); a01 = fma2(q0v.y, k1v.y, a01);
            a10 = fma2(q1v.x, k0v.x, a10); a10 = fma2(q1v.y, k0v.y, a10);
            a11 = fma2(q1v.x, k1v.x, a11); a11 = fma2(q1v.y, k1v.y, a11);
        }

        const int dyA = R - y0 + 7;
        const int dyB = dyA - 1;
        if (dyA >= d0 && dyA < d1) {
            float2 t = unpack2(a00);
            Qb[(dyA * 15 + dx0) * 1024 + y0 * 32 + x] = t.x + t.y;
            if (w < 7) {
                float2 u = unpack2(a01);
                Qb[(dyA * 15 + dx1) * 1024 + y0 * 32 + x] = u.x + u.y;
            }
        }
        if (dyB >= d0 && dyB < d1) {
            float2 t = unpack2(a10);
            Qb[(dyB * 15 + dx0) * 1024 + y1 * 32 + x] = t.x + t.y;
            if (w < 7) {
                float2 u = unpack2(a11);
                Qb[(dyB * 15 + dx1) * 1024 + y1 * 32 + x] = u.x + u.y;
            }
        }
    }
}

__global__ void __launch_bounds__(256) relqk_kernel(
        const float* __restrict__ Wrel, const float* __restrict__ brel) {
    extern __shared__ float sm[];
    const int bid = blockIdx.x;
    if (bid < 256) rel_body(sm, bid, Wrel, brel);
    else           qk_body(sm, bid - 256);
}

// ---------------------------------------------------------------------------
// Softmax: attn = softmax_w(g_logits + g_qk), written back to g_logits.
// ---------------------------------------------------------------------------
__global__ void __launch_bounds__(256) softmax_kernel() {
    __shared__ float att[7200];
    __shared__ float red[256];
    const int y = blockIdx.x, ng = blockIdx.y;
    const int tid = threadIdx.x;
    const int x = tid & 31, w = tid >> 5;
    float* L = g_logits + ng * 230400;
    const float* Q = g_qk + ng * 230400;

    for (int i = tid; i < 1800; i += 256) {
        int ww = i >> 3, x4 = i & 7;
        float4 a = *(const float4*)(L + ww * 1024 + y * 32 + x4 * 4);
        float4 b = *(const float4*)(Q + ww * 1024 + y * 32 + x4 * 4);
        *(float4*)(att + ww * 32 + x4 * 4) =
            make_float4(a.x + b.x, a.y + b.y, a.z + b.z, a.w + b.w);
    }
    __syncthreads();

    float lm = -1e30f;
    for (int ww = w; ww < 225; ww += 8) lm = fmaxf(lm, att[ww * 32 + x]);
    red[w * 32 + x] = lm;
    __syncthreads();
    float m = red[x];
    #pragma unroll
    for (int i = 1; i < 8; i++) m = fmaxf(m, red[i * 32 + x]);
    __syncthreads();
    float ls = 0.f;
    for (int ww = w; ww < 225; ww += 8) {
        float e = __expf(att[ww * 32 + x] - m);
        att[ww * 32 + x] = e;
        ls += e;
    }
    red[w * 32 + x] = ls;
    __syncthreads();
    float s = red[x];
    #pragma unroll
    for (int i = 1; i < 8; i++) s += red[i * 32 + x];
    float rinv = 1.f / s;
    for (int ww = w; ww < 225; ww += 8) att[ww * 32 + x] *= rinv;
    __syncthreads();

    for (int i = tid; i < 1800; i += 256) {
        int ww = i >> 3, x4 = i & 7;
        *(float4*)(L + ww * 1024 + y * 32 + x4 * 4) =
            *(const float4*)(att + ww * 32 + x4 * 4);
    }
}

// ---------------------------------------------------------------------------
// Fused agg + bias launch (grid 256).
//  bid < 128 : bias GEMM  g_aggb = attn . VbT   (64 pix x 128 c tile, K=225)
//  bid >= 128: V agg y-pair: g_agg = attn . V_unfold for rows (2yp, 2yp+1)
// ---------------------------------------------------------------------------
constexpr int AGG_FLOATS = 6400;            // max(bias 6400, agg slab 6072)
constexpr int AGG_BYTES  = AGG_FLOATS * 4;  // 25600

__device__ void bias_body(float* sm, int b) {
    float* a_s = sm;            // 32*72
    float* b_s = sm + 2304;     // 32*128

    const int pix0 = (b & 15) * 64;
    const int ng   = b >> 4;
    const int g    = ng & 1, n = ng >> 1;
    const int tid  = threadIdx.x;

    const float* attn = g_logits + ng * 230400;
    const float* vbt  = g_VbT + g * 28800;

    const int td = tid >> 4;
    const int tm = tid & 15;

    u64 acc[4][4];
    #pragma unroll
    for (int dd = 0; dd < 4; dd++)
        #pragma unroll
        for (int mq = 0; mq < 4; mq++) acc[dd][mq] = 0ull;

    const float4 z4 = make_float4(0.f, 0.f, 0.f, 0.f);

    for (int kb = 0; kb < 8; kb++) {
        const int k0 = kb * 32;
        #pragma unroll
        for (int r = 0; r < 2; r++) {
            int idx = tid + r * 256;
            int kk = idx >> 4, p4 = idx & 15;
            int w = k0 + kk;
            float4 v = (w < 225)
                ? *(const float4*)(attn + w * 1024 + pix0 + p4 * 4) : z4;
            *(float4*)(a_s + kk * 72 + p4 * 4) = v;
        }
        #pragma unroll
        for (int r = 0; r < 4; r++) {
            int idx = tid + r * 256;
            int kk = idx >> 5, c4 = idx & 31;
            int w = k0 + kk;
            float4 v = (w < 225)
                ? *(const float4*)(vbt + w * 128 + c4 * 4) : z4;
            *(float4*)(b_s + kk * 128 + c4 * 4) = v;
        }
        __syncthreads();

        #pragma unroll 8
        for (int kk = 0; kk < 32; kk++) {
            float4 av = *(const float4*)(a_s + kk * 72 + td * 4);
            u64 xv[4];
            #pragma unroll
            for (int mq = 0; mq < 4; mq++)
                xv[mq] = *(const u64*)(b_s + kk * 128 + 2 * tm + 32 * mq);
            u64 w0 = pack2(av.x, av.x), w1 = pack2(av.y, av.y);
            u64 w2 = pack2(av.z, av.z), w3 = pack2(av.w, av.w);
            #pragma unroll
            for (int mq = 0; mq < 4; mq++) {
                acc[0][mq] = fma2(w0, xv[mq], acc[0][mq]);
                acc[1][mq] = fma2(w1, xv[mq], acc[1][mq]);
                acc[2][mq] = fma2(w2, xv[mq], acc[2][mq]);
                acc[3][mq] = fma2(w3, xv[mq], acc[3][mq]);
            }
        }
        __syncthreads();
    }

    #pragma unroll
    for (int dd = 0; dd < 4; dd++) {
        const int pix = pix0 + td * 4 + dd;
        float* ap = g_aggb + (pix * 4 + n) * 256 + g * 128 + 2 * tm;
        #pragma unroll
        for (int mq = 0; mq < 4; mq++)
            *(float2*)(ap + 32 * mq) = unpack2(acc[dd][mq]);
    }
}

// one attn row set applied to the slab (16 channels per thread)
__device__ __forceinline__ void agg_rank1(
        u64* acc, const float* __restrict__ pA, const float* slab,
        int x, int cbase) {
    #pragma unroll 5
    for (int dx = 0; dx < 15; dx++) {
        float aw = pA[dx << 10];
        u64 a2 = pack2(aw, aw);
        const float* vp = slab + (x + dx) * 132 + cbase;
        ulonglong2 v0 = *(const ulonglong2*)(vp);
        ulonglong2 v1 = *(const ulonglong2*)(vp + 4);
        ulonglong2 v2 = *(const ulonglong2*)(vp + 8);
        ulonglong2 v3 = *(const ulonglong2*)(vp + 12);
        acc[0] = fma2(a2, v0.x, acc[0]); acc[1] = fma2(a2, v0.y, acc[1]);
        acc[2] = fma2(a2, v1.x, acc[2]); acc[3] = fma2(a2, v1.y, acc[3]);
        acc[4] = fma2(a2, v2.x, acc[4]); acc[5] = fma2(a2, v2.y, acc[5]);
        acc[6] = fma2(a2, v3.x, acc[6]); acc[7] = fma2(a2, v3.y, acc[7]);
    }
}

__device__ void agg_body(float* sm, int b) {
    float* slab = sm;                 // [46][132]

    const int yp = b & 15;
    const int y0 = yp * 2, y1 = y0 + 1;
    const int ng = b >> 4;
    const int g = ng & 1, n = ng >> 1;
    const int tid = threadIdx.x;
    const int x = tid & 31, w = tid >> 5;
    const int cbase = w * 16;

    const float* vT = g_vT + ng * 131072;
    const float* Lb = g_logits + ng * 230400;

    // permanent zero edges of slab
    for (int i = tid; i < 14 * 32; i += 256) {
        int e = i >> 5, c4 = i & 31;
        int px = (e < 7) ? e : e + 32;
        *(float4*)(slab + px * 132 + c4 * 4) = make_float4(0.f, 0.f, 0.f, 0.f);
    }

    u64 acc0[8], acc1[8];
    #pragma unroll
    for (int j = 0; j < 8; j++) { acc0[j] = 0; acc1[j] = 0; }

    const int iy_lo = (y0 - 7 < 0) ? 0 : y0 - 7;
    const int iy_hi = (y0 + 8 > 31) ? 31 : y0 + 8;

    for (int iy = iy_lo; iy <= iy_hi; iy++) {
        __syncthreads();
        #pragma unroll
        for (int r = 0; r < 4; r++) {
            int i = tid + r * 256;
            int ix = i >> 5, c4 = i & 31;
            *(float4*)(slab + (ix + 7) * 132 + c4 * 4) =
                *(const float4*)(vT + (iy * 32 + ix) * 128 + c4 * 4);
        }
        __syncthreads();

        const int dyA = iy - y0 + 7;     // 0..15 (15 = invalid for y0)
        const int dyB = dyA - 1;         // -1..14 (-1 = invalid for y1)
        const bool vA = (dyA <= 14);
        const bool vB = (dyB >= 0);

        if (vA && vB) {
            const float* pA = Lb + (dyA * 15) * 1024 + y0 * 32 + x;
            const float* pB = Lb + (dyB * 15) * 1024 + y1 * 32 + x;
            #pragma unroll 5
            for (int dx = 0; dx < 15; dx++) {
                float aw0 = pA[dx << 10];
                float aw1 = pB[dx << 10];
                u64 a0 = pack2(aw0, aw0), a1 = pack2(aw1, aw1);
                const float* vp = slab + (x + dx) * 132 + cbase;
                ulonglong2 v0 = *(const ulonglong2*)(vp);
                ulonglong2 v1 = *(const ulonglong2*)(vp + 4);
                ulonglong2 v2 = *(const ulonglong2*)(vp + 8);
                ulonglong2 v3 = *(const ulonglong2*)(vp + 12);
                acc0[0] = fma2(a0, v0.x, acc0[0]); acc0[1] = fma2(a0, v0.y, acc0[1]);
                acc0[2] = fma2(a0, v1.x, acc0[2]); acc0[3] = fma2(a0, v1.y, acc0[3]);
                acc0[4] = fma2(a0, v2.x, acc0[4]); acc0[5] = fma2(a0, v2.y, acc0[5]);
                acc0[6] = fma2(a0, v3.x, acc0[6]); acc0[7] = fma2(a0, v3.y, acc0[7]);
                acc1[0] = fma2(a1, v0.x, acc1[0]); acc1[1] = fma2(a1, v0.y, acc1[1]);
                acc1[2] = fma2(a1, v1.x, acc1[2]); acc1[3] = fma2(a1, v1.y, acc1[3]);
                acc1[4] = fma2(a1, v2.x, acc1[4]); acc1[5] = fma2(a1, v2.y, acc1[5]);
                acc1[6] = fma2(a1, v3.x, acc1[6]); acc1[7] = fma2(a1, v3.y, acc1[7]);
            }
        } else if (vA) {
            agg_rank1(acc0, Lb + (dyA * 15) * 1024 + y0 * 32 + x, slab, x, cbase);
        } else {
            agg_rank1(acc1, Lb + (dyB * 15) * 1024 + y1 * 32 + x, slab, x, cbase);
        }
    }

    float* a0p = g_agg + ((y0 * 32 + x) * 4 + n) * 256 + g * 128 + cbase;
    float* a1p = g_agg + ((y1 * 32 + x) * 4 + n) * 256 + g * 128 + cbase;
    #pragma unroll
    for (int j = 0; j < 8; j++) {
        *(float2*)(a0p + 2 * j) = unpack2(acc0[j]);
        *(float2*)(a1p + 2 * j) = unpack2(acc1[j]);
    }
}

__global__ void __launch_bounds__(256) aggbias_kernel() {
    extern __shared__ float sm[];
    const int bid = blockIdx.x;
    if (bid < 128) bias_body(sm, bid);
    else           agg_body(sm, bid - 128);
}

// ---------------------------------------------------------------------------
// Output FC: out[r, d] = sum_c (agg+aggb)[r, c] * Wfc[d, c] + bfc[d]
// ---------------------------------------------------------------------------
__global__ void __launch_bounds__(256) fc_kernel(
        const float* __restrict__ Wfc, const float* __restrict__ bfc,
        float* __restrict__ out) {
    __shared__ float w_s[32 * 68];
    __shared__ float x_s[32 * 128];

    const int r0 = blockIdx.x * 64;
    const int d0 = blockIdx.y * 128;
    const int tid = threadIdx.x;
    const int td = tid >> 4;
    const int tm = tid & 15;

    u64 acc[4][4];
    #pragma unroll
    for (int mq = 0; mq < 4; mq++) {
        int d = d0 + 2 * tm + 32 * mq;
        u64 bb = pack2(bfc[d], bfc[d + 1]);
        #pragma unroll
        for (int rr = 0; rr < 4; rr++) acc[rr][mq] = bb;
    }

    const int lrq = tid >> 3;
    const int lc4 = tid & 7;
    const int ld  = tid & 127;
    const int lch = tid >> 7;

    for (int kb = 0; kb < 8; kb++) {
        const int k0 = kb * 32;
        {
            const int i1 = (r0 + lrq) * 256 + k0 + lc4 * 4;
            const int i2 = (r0 + lrq + 32) * 256 + k0 + lc4 * 4;
            float4 fa = *(const float4*)(g_agg + i1);
            float4 ba = *(const float4*)(g_aggb + i1);
            float4 fb = *(const float4*)(g_agg + i2);
            float4 bb = *(const float4*)(g_aggb + i2);
            fa.x += ba.x; fa.y += ba.y; fa.z += ba.z; fa.w += ba.w;
            fb.x += bb.x; fb.y += bb.y; fb.z += bb.z; fb.w += bb.w;
            w_s[(lc4 * 4 + 0) * 68 + lrq] = fa.x;
            w_s[(lc4 * 4 + 1) * 68 + lrq] = fa.y;
            w_s[(lc4 * 4 + 2) * 68 + lrq] = fa.z;
            w_s[(lc4 * 4 + 3) * 68 + lrq] = fa.w;
            w_s[(lc4 * 4 + 0) * 68 + lrq + 32] = fb.x;
            w_s[(lc4 * 4 + 1) * 68 + lrq + 32] = fb.y;
            w_s[(lc4 * 4 + 2) * 68 + lrq + 32] = fb.z;
            w_s[(lc4 * 4 + 3) * 68 + lrq + 32] = fb.w;
        }
        #pragma unroll
        for (int i = 0; i < 4; i++) {
            int cq = lch * 4 + i;
            float4 f = *(const float4*)(Wfc + (d0 + ld) * 256 + k0 + cq * 4);
            x_s[(cq * 4 + 0) * 128 + ld] = f.x;
            x_s[(cq * 4 + 1) * 128 + ld] = f.y;
            x_s[(cq * 4 + 2) * 128 + ld] = f.z;
            x_s[(cq * 4 + 3) * 128 + ld] = f.w;
        }
        __syncthreads();

        #pragma unroll 8
        for (int kk = 0; kk < 32; kk++) {
            float4 wv = *(const float4*)(w_s + kk * 68 + td * 4);
            u64 xv[4];
            #pragma unroll
            for (int mq = 0; mq < 4; mq++)
                xv[mq] = *(const u64*)(x_s + kk * 128 + 2 * tm + 32 * mq);
            u64 w0 = pack2(wv.x, wv.x), w1 = pack2(wv.y, wv.y);
            u64 w2 = pack2(wv.z, wv.z), w3 = pack2(wv.w, wv.w);
            #pragma unroll
            for (int mq = 0; mq < 4; mq++) {
                acc[0][mq] = fma2(w0, xv[mq], acc[0][mq]);
                acc[1][mq] = fma2(w1, xv[mq], acc[1][mq]);
                acc[2][mq] = fma2(w2, xv[mq], acc[2][mq]);
                acc[3][mq] = fma2(w3, xv[mq], acc[3][mq]);
            }
        }
        __syncthreads();
    }

    #pragma unroll
    for (int rr = 0; rr < 4; rr++) {
        float* op = out + (r0 + td * 4 + rr) * 256 + d0 + 2 * tm;
        #pragma unroll
        for (int mq = 0; mq < 4; mq++)
            *(float2*)(op + 32 * mq) = unpack2(acc[rr][mq]);
    }
}

// ---------------------------------------------------------------------------
extern "C" void kernel_launch(void* const* d_in, const int* in_sizes, int n_in,
                              void* d_out, int out_size) {
    const float* q    = (const float*)d_in[0];
    const float* k    = (const float*)d_in[1];
    const float* v    = (const float*)d_in[2];
    const float* Wq   = (const float*)d_in[3];
    const float* bq   = (const float*)d_in[4];
    const float* Wk   = (const float*)d_in[5];
    const float* bk   = (const float*)d_in[6];
    const float* Wv   = (const float*)d_in[7];
    const float* bv   = (const float*)d_in[8];
    const float* Wrel = (const float*)d_in[9];
    const float* brel = (const float*)d_in[10];
    const float* Vb   = (const float*)d_in[11];
    const float* Wfc  = (const float*)d_in[12];
    const float* bfc  = (const float*)d_in[13];
    float* out = (float*)d_out;

    cudaFuncSetAttribute(relqk_kernel, cudaFuncAttributeMaxDynamicSharedMemorySize,
                         QK_SMEM_BYTES);
    cudaFuncSetAttribute(aggbias_kernel, cudaFuncAttributeMaxDynamicSharedMemorySize,
                         AGG_BYTES);

    dim3 pg(32, 4, 4);
    proj_kernel<<<pg, 128>>>(q, k, v, Wq, bq, Wk, bk, Wv, bv, Vb);

    relqk_kernel<<<512, 256, QK_SMEM_BYTES>>>(Wrel, brel);

    dim3 sg(32, 8);
    softmax_kernel<<<sg, 256>>>();

    aggbias_kernel<<<256, 256, AGG_BYTES>>>();

    dim3 fg(64, 2);
    fc_kernel<<<fg, 256>>>(Wfc, bfc, out);
}

// round 9
// speedup vs baseline: 1.2585x; 1.0487x over previous
#include <cuda_runtime.h>

typedef unsigned long long u64;

// ---------------- f32x2 packed-math helpers (sm_103a) ----------------
__device__ __forceinline__ u64 fma2(u64 a, u64 b, u64 c) {
    u64 d;
    asm("fma.rn.f32x2 %0, %1, %2, %3;" : "=l"(d) : "l"(a), "l"(b), "l"(c));
    return d;
}
__device__ __forceinline__ u64 pack2(float lo, float hi) {
    u64 d;
    asm("mov.b64 %0, {%1, %2};" : "=l"(d) : "f"(lo), "f"(hi));
    return d;
}
__device__ __forceinline__ float2 unpack2(u64 v) {
    float2 r;
    asm("mov.b64 {%0, %1}, %2;" : "=f"(r.x), "=f"(r.y) : "l"(v));
    return r;
}
// ---------------- cp.async helpers ----------------
__device__ __forceinline__ void cp16(unsigned s, const void* g) {
    asm volatile("cp.async.cg.shared.global [%0], [%1], 16;" :: "r"(s), "l"(g));
}
__device__ __forceinline__ void cp_commit() {
    asm volatile("cp.async.commit_group;");
}
__device__ __forceinline__ void cp_wait0() {
    asm volatile("cp.async.wait_group 0;" ::: "memory");
}

// Scratch (zero-initialized device globals)
__device__ float g_qproj[4 * 256 * 1024];   // [n][c][pix] (unscaled, for rel)
__device__ float g_qT[8 * 1024 * 128];      // [ng][pix][c], scaled by 1/T
__device__ float g_kT[8 * 1024 * 128];
__device__ float g_vT[8 * 1024 * 128];
__device__ float g_VbT[2 * 225 * 128];      // [g][w][c]
__device__ float g_agg[1024 * 4 * 256];     // attn . V
__device__ float g_aggb[1024 * 4 * 256];    // attn . V_bias
__device__ float g_logits[8 * 225 * 1024];  // [ng][wpos][pix]  rel / then attn
__device__ float g_qk[8 * 225 * 1024];      // [ng][wpos][pix]  raw qk dots

// ---------------------------------------------------------------------------
// proj: Y = W.X + b ; writes qT/kT/vT (transposed, q scaled) + qproj.
// z = 3 slice transposes V_bias. 128 threads, tile 64d x 128m, micro 8x8.
// ---------------------------------------------------------------------------
__global__ void __launch_bounds__(128) proj_kernel(
        const float* __restrict__ q, const float* __restrict__ k,
        const float* __restrict__ v,
        const float* __restrict__ Wq, const float* __restrict__ bq,
        const float* __restrict__ Wk, const float* __restrict__ bk,
        const float* __restrict__ Wv, const float* __restrict__ bv,
        const float* __restrict__ Vb) {
    __shared__ float w_s[32 * 68];    // [kk][d]
    __shared__ float x_s[32 * 128];   // [kk][m]

    const int p   = blockIdx.z;
    const int tid = threadIdx.x;

    if (p == 3) {   // V_bias transpose: [g][c][w] -> [g][w][c]
        int idx = (blockIdx.x * 4 + blockIdx.y) * 128 + tid;
        for (int i = idx; i < 57600; i += 16384) {
            int g = i / 28800, r = i - g * 28800;
            int w = r >> 7, c = r & 127;
            g_VbT[g * 28800 + r] = Vb[g * 28800 + c * 225 + w];
        }
        return;
    }

    const int m0 = blockIdx.x * 128;
    const int d0 = blockIdx.y * 64;
    const int n  = m0 >> 10;
    const int hw0 = m0 & 1023;

    const float *X, *Wm, *B;
    if (p == 0)      { X = q; Wm = Wq; B = bq; }
    else if (p == 1) { X = k; Wm = Wk; B = bk; }
    else             { X = v; Wm = Wv; B = bv; }

    const int td = tid >> 4;   // 0..7 -> d rows td*8..+7
    const int tm = tid & 15;   // m cols 2tm+32mq

    u64 acc[8][4];
    #pragma unroll
    for (int dd = 0; dd < 8; dd++) {
        float b = B[d0 + td * 8 + dd];
        u64 bb = pack2(b, b);
        #pragma unroll
        for (int mq = 0; mq < 4; mq++) acc[dd][mq] = bb;
    }

    const int dl   = tid >> 1;
    const int half = tid & 1;

    for (int kb = 0; kb < 8; kb++) {
        const int k0 = kb * 32;
        {
            const float* src = Wm + (d0 + dl) * 256 + k0 + half * 16;
            #pragma unroll
            for (int qq = 0; qq < 4; qq++) {
                float4 f = *(const float4*)(src + qq * 4);
                int kk = half * 16 + qq * 4;
                w_s[(kk + 0) * 68 + dl] = f.x;
                w_s[(kk + 1) * 68 + dl] = f.y;
                w_s[(kk + 2) * 68 + dl] = f.z;
                w_s[(kk + 3) * 68 + dl] = f.w;
            }
        }
        #pragma unroll
        for (int r = 0; r < 8; r++) {
            int idx = tid + r * 128;
            int kk = idx >> 5, m4 = idx & 31;
            *(float4*)(x_s + kk * 128 + m4 * 4) =
                *(const float4*)(X + (n * 256 + k0 + kk) * 1024 + hw0 + m4 * 4);
        }
        __syncthreads();

        #pragma unroll 8
        for (int kk = 0; kk < 32; kk++) {
            float4 wa = *(const float4*)(w_s + kk * 68 + td * 8);
            float4 wb = *(const float4*)(w_s + kk * 68 + td * 8 + 4);
            u64 xv[4];
            #pragma unroll
            for (int mq = 0; mq < 4; mq++)
                xv[mq] = *(const u64*)(x_s + kk * 128 + 2 * tm + 32 * mq);
            u64 wr[8];
            wr[0] = pack2(wa.x, wa.x); wr[1] = pack2(wa.y, wa.y);
            wr[2] = pack2(wa.z, wa.z); wr[3] = pack2(wa.w, wa.w);
            wr[4] = pack2(wb.x, wb.x); wr[5] = pack2(wb.y, wb.y);
            wr[6] = pack2(wb.z, wb.z); wr[7] = pack2(wb.w, wb.w);
            #pragma unroll
            for (int dd = 0; dd < 8; dd++)
                #pragma unroll
                for (int mq = 0; mq < 4; mq++)
                    acc[dd][mq] = fma2(wr[dd], xv[mq], acc[dd][mq]);
        }
        __syncthreads();
    }

    // transposed store -> [ng][pix][c]
    const int gg  = d0 >> 7;
    const int ng  = n * 2 + gg;
    const int ch0 = (d0 & 127) + td * 8;
    float* T = (p == 0) ? g_qT : (p == 1) ? g_kT : g_vT;
    const float s = (p == 0) ? 0.08838834764831845f : 1.f;
    #pragma unroll
    for (int mq = 0; mq < 4; mq++) {
        float2 t[8];
        #pragma unroll
        for (int dd = 0; dd < 8; dd++) t[dd] = unpack2(acc[dd][mq]);
        float* b0 = T + ng * 131072 + (hw0 + 2 * tm + 32 * mq) * 128 + ch0;
        *(float4*)(b0)       = make_float4(t[0].x*s, t[1].x*s, t[2].x*s, t[3].x*s);
        *(float4*)(b0 + 4)   = make_float4(t[4].x*s, t[5].x*s, t[6].x*s, t[7].x*s);
        *(float4*)(b0 + 128) = make_float4(t[0].y*s, t[1].y*s, t[2].y*s, t[3].y*s);
        *(float4*)(b0 + 132) = make_float4(t[4].y*s, t[5].y*s, t[6].y*s, t[7].y*s);
    }
    if (p == 0) {   // [c][pix] copy for rel GEMM
        #pragma unroll
        for (int dd = 0; dd < 8; dd++) {
            float* yp = g_qproj + (n * 256 + d0 + td * 8 + dd) * 1024 + hw0 + 2 * tm;
            #pragma unroll
            for (int mq = 0; mq < 4; mq++)
                *(float2*)(yp + 32 * mq) = unpack2(acc[dd][mq]);
        }
    }
}

// ---------------------------------------------------------------------------
// Fused QK + rel-GEMM kernel (grid 384).
//  bid < 128 : qk dots -> g_qk (one block per (yp, ng), double-buffered slab)
//  bid >= 128: rel -> g_logits (masked, +brel)
// ---------------------------------------------------------------------------
constexpr int QK_Q0   = 0;
constexpr int QK_Q1   = 32 * 132;              // 4224
constexpr int QK_SLAB = 2 * 32 * 132;          // 8448
constexpr int QK_SLABSZ = 46 * 132;            // 6072
constexpr int QK_SMEM_FLOATS = QK_SLAB + 2 * QK_SLABSZ;   // 20592
constexpr int QK_SMEM_BYTES  = QK_SMEM_FLOATS * 4;        // 82368

__device__ void rel_body(float* sm, int bid,
                         const float* __restrict__ Wrel,
                         const float* __restrict__ brel) {
    float* w_s = sm;            // 32*68
    float* x_s = sm + 2176;     // 32*128

    const int pix0 = (bid & 7) * 128;
    const int d0   = ((bid >> 3) & 3) * 64;
    const int ng   = bid >> 5;
    const int g    = ng & 1;
    const int tid  = threadIdx.x;

    const float* Wg = Wrel + g * 225 * 128;
    const float* X  = g_qproj + ng * 131072;

    const int td = tid >> 4;
    const int tm = tid & 15;

    u64 acc[4][4];
    #pragma unroll
    for (int dd = 0; dd < 4; dd++)
        #pragma unroll
        for (int mq = 0; mq < 4; mq++) acc[dd][mq] = 0ull;

    const int ldq = tid >> 3;
    const int lc4 = tid & 7;
    const int lk  = tid >> 5;
    const int lm4 = tid & 31;

    for (int kb = 0; kb < 4; kb++) {
        const int k0 = kb * 32;
        {
            float4 z = make_float4(0.f, 0.f, 0.f, 0.f);
            float4 fa = (d0 + ldq < 225)
                ? *(const float4*)(Wg + (d0 + ldq) * 128 + k0 + lc4 * 4) : z;
            float4 fb = (d0 + ldq + 32 < 225)
                ? *(const float4*)(Wg + (d0 + ldq + 32) * 128 + k0 + lc4 * 4) : z;
            w_s[(lc4 * 4 + 0) * 68 + ldq] = fa.x;
            w_s[(lc4 * 4 + 1) * 68 + ldq] = fa.y;
            w_s[(lc4 * 4 + 2) * 68 + ldq] = fa.z;
            w_s[(lc4 * 4 + 3) * 68 + ldq] = fa.w;
            w_s[(lc4 * 4 + 0) * 68 + ldq + 32] = fb.x;
            w_s[(lc4 * 4 + 1) * 68 + ldq + 32] = fb.y;
            w_s[(lc4 * 4 + 2) * 68 + ldq + 32] = fb.z;
            w_s[(lc4 * 4 + 3) * 68 + ldq + 32] = fb.w;
        }
        #pragma unroll
        for (int r = 0; r < 4; r++) {
            *(float4*)(x_s + (lk + 8 * r) * 128 + lm4 * 4) =
                *(const float4*)(X + (k0 + lk + 8 * r) * 1024 + pix0 + lm4 * 4);
        }
        __syncthreads();

        #pragma unroll 8
        for (int kk = 0; kk < 32; kk++) {
            float4 wv = *(const float4*)(w_s + kk * 68 + td * 4);
            u64 xv[4];
            #pragma unroll
            for (int mq = 0; mq < 4; mq++)
                xv[mq] = *(const u64*)(x_s + kk * 128 + 2 * tm + 32 * mq);
            u64 w0 = pack2(wv.x, wv.x), w1 = pack2(wv.y, wv.y);
            u64 w2 = pack2(wv.z, wv.z), w3 = pack2(wv.w, wv.w);
            #pragma unroll
            for (int mq = 0; mq < 4; mq++) {
                acc[0][mq] = fma2(w0, xv[mq], acc[0][mq]);
                acc[1][mq] = fma2(w1, xv[mq], acc[1][mq]);
                acc[2][mq] = fma2(w2, xv[mq], acc[2][mq]);
                acc[3][mq] = fma2(w3, xv[mq], acc[3][mq]);
            }
        }
        __syncthreads();
    }

    float* Lb = g_logits + ng * 230400;
    #pragma unroll
    for (int dd = 0; dd < 4; dd++) {
        const int wpos = d0 + td * 4 + dd;
        if (wpos >= 225) continue;
        const float bv = brel[g * 225 + wpos];
        const int dy = wpos / 15;
        const int dxw = wpos - dy * 15;
        #pragma unroll
        for (int mq = 0; mq < 4; mq++) {
            const int pix = pix0 + 2 * tm + 32 * mq;
            const int y = pix >> 5, x = pix & 31;
            const int iy = y + dy - 7;
            const bool ry = (iy >= 0) && (iy < 32);
            const int ix0 = x + dxw - 7;
            float2 t = unpack2(acc[dd][mq]);
            float v0 = (ry && ix0 >= 0 && ix0 < 32) ? t.x + bv : -1e8f;
            float v1 = (ry && ix0 + 1 >= 0 && ix0 + 1 < 32) ? t.y + bv : -1e8f;
            *(float2*)(Lb + wpos * 1024 + pix) = make_float2(v0, v1);
        }
    }
}

__device__ void qk_body(float* sm, unsigned smb, int b) {
    float* q0s = sm + QK_Q0;
    float* q1s = sm + QK_Q1;

    const int yp = b & 15;
    const int y0 = yp * 2, y1 = y0 + 1;
    const int ng = b >> 4;
    const int tid = threadIdx.x;
    const int x = tid & 31, w = tid >> 5;

    const float* qT = g_qT + ng * 131072;
    const float* kT = g_kT + ng * 131072;
    float* Qb = g_qk + ng * 230400;

    for (int i = tid; i < 1024; i += 256) {
        int xx = i >> 5, c4 = i & 31;
        *(float4*)(q0s + xx * 132 + c4 * 4) =
            *(const float4*)(qT + (y0 * 32 + xx) * 128 + c4 * 4);
        *(float4*)(q1s + xx * 132 + c4 * 4) =
            *(const float4*)(qT + (y1 * 32 + xx) * 128 + c4 * 4);
    }
    // zero permanent edges of BOTH slab buffers
    for (int i = tid; i < 2 * 14 * 32; i += 256) {
        int buf = i / 448, r = i - buf * 448;
        int e = r >> 5, c4 = r & 31;
        int px = (e < 7) ? e : e + 32;
        *(float4*)(sm + QK_SLAB + buf * QK_SLABSZ + px * 132 + c4 * 4) =
            make_float4(0.f, 0.f, 0.f, 0.f);
    }

    const int iy_lo = (y0 - 7 < 0) ? 0 : y0 - 7;
    const int iy_hi = (y0 + 8 > 31) ? 31 : y0 + 8;

    const int lix = tid >> 5 << 2;   // unused placeholder avoided below
    (void)lix;

    // prime buffer 0
    {
        #pragma unroll
        for (int r = 0; r < 4; r++) {
            int i = tid + r * 256;
            int ix = i >> 5, c4 = i & 31;
            cp16(smb + (QK_SLAB + (ix + 7) * 132 + c4 * 4) * 4,
                 kT + (iy_lo * 32 + ix) * 128 + c4 * 4);
        }
        cp_commit();
        cp_wait0();
    }
    __syncthreads();

    const int dx0 = w;
    const int dx1 = (w < 7) ? w + 8 : 0;
    int cur = 0;

    for (int iy = iy_lo; iy <= iy_hi; iy++) {
        if (iy < iy_hi) {
            const int nb = cur ^ 1;
            #pragma unroll
            for (int r = 0; r < 4; r++) {
                int i = tid + r * 256;
                int ix = i >> 5, c4 = i & 31;
                cp16(smb + (QK_SLAB + nb * QK_SLABSZ + (ix + 7) * 132 + c4 * 4) * 4,
                     kT + ((iy + 1) * 32 + ix) * 128 + c4 * 4);
            }
            cp_commit();
        }
        const float* slab = sm + QK_SLAB + cur * QK_SLABSZ;

        u64 a00 = 0, a01 = 0, a10 = 0, a11 = 0;
        const float* qp0 = q0s + x * 132;
        const float* qp1 = q1s + x * 132;
        const float* k0p = slab + (x + dx0) * 132;
        const float* k1p = slab + (x + dx1) * 132;
        #pragma unroll 8
        for (int c4 = 0; c4 < 32; c4++) {
            ulonglong2 q0v = *(const ulonglong2*)(qp0 + 4 * c4);
            ulonglong2 q1v = *(const ulonglong2*)(qp1 + 4 * c4);
            ulonglong2 k0v = *(const ulonglong2*)(k0p + 4 * c4);
            ulonglong2 k1v = *(const ulonglong2*)(k1p + 4 * c4);
            a00 = fma2(q0v.x, k0v.x, a00); a00 = fma2(q0v.y, k0v.y, a00);
            a01 = fma2(q0v.x, k1v.x, a01); a01 = fma2(q0v.y, k1v.y, a01);
            a10 = fma2(q1v.x, k0v.x, a10); a10 = fma2(q1v.y, k0v.y, a10);
            a11 = fma2(q1v.x, k1v.x, a11); a11 = fma2(q1v.y, k1v.y, a11);
        }

        const int dyA = iy - y0 + 7;     // 0..15; 15 invalid for y0
        const int dyB = dyA - 1;         // -1..14; -1 invalid for y1
        if (dyA <= 14) {
            float2 t = unpack2(a00);
            Qb[(dyA * 15 + dx0) * 1024 + y0 * 32 + x] = t.x + t.y;
            if (w < 7) {
                float2 u = unpack2(a01);
                Qb[(dyA * 15 + dx1) * 1024 + y0 * 32 + x] = u.x + u.y;
            }
        }
        if (dyB >= 0) {
            float2 t = unpack2(a10);
            Qb[(dyB * 15 + dx0) * 1024 + y1 * 32 + x] = t.x + t.y;
            if (w < 7) {
                float2 u = unpack2(a11);
                Qb[(dyB * 15 + dx1) * 1024 + y1 * 32 + x] = u.x + u.y;
            }
        }

        cp_wait0();
        __syncthreads();
        cur ^= 1;
    }
}

__global__ void __launch_bounds__(256) relqk_kernel(
        const float* __restrict__ Wrel, const float* __restrict__ brel) {
    extern __shared__ float sm[];
    unsigned smb = (unsigned)__cvta_generic_to_shared(sm);
    const int bid = blockIdx.x;
    if (bid < 128) qk_body(sm, smb, bid);
    else           rel_body(sm, bid - 128, Wrel, brel);
}

// ---------------------------------------------------------------------------
// Softmax: attn = softmax_w(g_logits + g_qk), written back to g_logits.
// ---------------------------------------------------------------------------
__global__ void __launch_bounds__(256) softmax_kernel() {
    __shared__ float att[7200];
    __shared__ float red[256];
    const int y = blockIdx.x, ng = blockIdx.y;
    const int tid = threadIdx.x;
    const int x = tid & 31, w = tid >> 5;
    float* L = g_logits + ng * 230400;
    const float* Q = g_qk + ng * 230400;

    for (int i = tid; i < 1800; i += 256) {
        int ww = i >> 3, x4 = i & 7;
        float4 a = *(const float4*)(L + ww * 1024 + y * 32 + x4 * 4);
        float4 b = *(const float4*)(Q + ww * 1024 + y * 32 + x4 * 4);
        *(float4*)(att + ww * 32 + x4 * 4) =
            make_float4(a.x + b.x, a.y + b.y, a.z + b.z, a.w + b.w);
    }
    __syncthreads();

    float lm = -1e30f;
    for (int ww = w; ww < 225; ww += 8) lm = fmaxf(lm, att[ww * 32 + x]);
    red[w * 32 + x] = lm;
    __syncthreads();
    float m = red[x];
    #pragma unroll
    for (int i = 1; i < 8; i++) m = fmaxf(m, red[i * 32 + x]);
    __syncthreads();
    float ls = 0.f;
    for (int ww = w; ww < 225; ww += 8) {
        float e = __expf(att[ww * 32 + x] - m);
        att[ww * 32 + x] = e;
        ls += e;
    }
    red[w * 32 + x] = ls;
    __syncthreads();
    float s = red[x];
    #pragma unroll
    for (int i = 1; i < 8; i++) s += red[i * 32 + x];
    float rinv = 1.f / s;
    for (int ww = w; ww < 225; ww += 8) att[ww * 32 + x] *= rinv;
    __syncthreads();

    for (int i = tid; i < 1800; i += 256) {
        int ww = i >> 3, x4 = i & 7;
        *(float4*)(L + ww * 1024 + y * 32 + x4 * 4) =
            *(const float4*)(att + ww * 32 + x4 * 4);
    }
}

// ---------------------------------------------------------------------------
// Fused agg + bias launch (grid 256).
//  bid < 128 : bias GEMM  g_aggb = attn . VbT   (64 pix x 128 c tile, K=225)
//  bid >= 128: V agg y-pair: g_agg = attn . V_unfold for rows (2yp, 2yp+1)
//              double-buffered V slab via cp.async
// ---------------------------------------------------------------------------
constexpr int AGG_SLABSZ = 46 * 132;            // 6072
constexpr int AGG_FLOATS = 2 * AGG_SLABSZ;      // 12144
constexpr int AGG_BYTES  = AGG_FLOATS * 4;      // 48576

__device__ void bias_body(float* sm, int b) {
    float* a_s = sm;            // 32*72
    float* b_s = sm + 2304;     // 32*128

    const int pix0 = (b & 15) * 64;
    const int ng   = b >> 4;
    const int g    = ng & 1, n = ng >> 1;
    const int tid  = threadIdx.x;

    const float* attn = g_logits + ng * 230400;
    const float* vbt  = g_VbT + g * 28800;

    const int td = tid >> 4;
    const int tm = tid & 15;

    u64 acc[4][4];
    #pragma unroll
    for (int dd = 0; dd < 4; dd++)
        #pragma unroll
        for (int mq = 0; mq < 4; mq++) acc[dd][mq] = 0ull;

    const float4 z4 = make_float4(0.f, 0.f, 0.f, 0.f);

    for (int kb = 0; kb < 8; kb++) {
        const int k0 = kb * 32;
        #pragma unroll
        for (int r = 0; r < 2; r++) {
            int idx = tid + r * 256;
            int kk = idx >> 4, p4 = idx & 15;
            int w = k0 + kk;
            float4 v = (w < 225)
                ? *(const float4*)(attn + w * 1024 + pix0 + p4 * 4) : z4;
            *(float4*)(a_s + kk * 72 + p4 * 4) = v;
        }
        #pragma unroll
        for (int r = 0; r < 4; r++) {
            int idx = tid + r * 256;
            int kk = idx >> 5, c4 = idx & 31;
            int w = k0 + kk;
            float4 v = (w < 225)
                ? *(const float4*)(vbt + w * 128 + c4 * 4) : z4;
            *(float4*)(b_s + kk * 128 + c4 * 4) = v;
        }
        __syncthreads();

        #pragma unroll 8
        for (int kk = 0; kk < 32; kk++) {
            float4 av = *(const float4*)(a_s + kk * 72 + td * 4);
            u64 xv[4];
            #pragma unroll
            for (int mq = 0; mq < 4; mq++)
                xv[mq] = *(const u64*)(b_s + kk * 128 + 2 * tm + 32 * mq);
            u64 w0 = pack2(av.x, av.x), w1 = pack2(av.y, av.y);
            u64 w2 = pack2(av.z, av.z), w3 = pack2(av.w, av.w);
            #pragma unroll
            for (int mq = 0; mq < 4; mq++) {
                acc[0][mq] = fma2(w0, xv[mq], acc[0][mq]);
                acc[1][mq] = fma2(w1, xv[mq], acc[1][mq]);
                acc[2][mq] = fma2(w2, xv[mq], acc[2][mq]);
                acc[3][mq] = fma2(w3, xv[mq], acc[3][mq]);
            }
        }
        __syncthreads();
    }

    #pragma unroll
    for (int dd = 0; dd < 4; dd++) {
        const int pix = pix0 + td * 4 + dd;
        float* ap = g_aggb + (pix * 4 + n) * 256 + g * 128 + 2 * tm;
        #pragma unroll
        for (int mq = 0; mq < 4; mq++)
            *(float2*)(ap + 32 * mq) = unpack2(acc[dd][mq]);
    }
}

__device__ void agg_body(float* sm, unsigned smb, int b) {
    const int yp = b & 15;
    const int y0 = yp * 2, y1 = y0 + 1;
    const int ng = b >> 4;
    const int g = ng & 1, n = ng >> 1;
    const int tid = threadIdx.x;
    const int x = tid & 31, w = tid >> 5;
    const int cbase = w * 16;

    const float* vT = g_vT + ng * 131072;
    const float* Lb = g_logits + ng * 230400;

    // permanent zero edges of BOTH slab buffers
    for (int i = tid; i < 2 * 14 * 32; i += 256) {
        int buf = i / 448, r = i - buf * 448;
        int e = r >> 5, c4 = r & 31;
        int px = (e < 7) ? e : e + 32;
        *(float4*)(sm + buf * AGG_SLABSZ + px * 132 + c4 * 4) =
            make_float4(0.f, 0.f, 0.f, 0.f);
    }

    u64 acc0[8], acc1[8];
    #pragma unroll
    for (int j = 0; j < 8; j++) { acc0[j] = 0; acc1[j] = 0; }

    const int iy_lo = (y0 - 7 < 0) ? 0 : y0 - 7;
    const int iy_hi = (y0 + 8 > 31) ? 31 : y0 + 8;

    // prime buffer 0
    {
        #pragma unroll
        for (int r = 0; r < 4; r++) {
            int i = tid + r * 256;
            int ix = i >> 5, c4 = i & 31;
            cp16(smb + ((ix + 7) * 132 + c4 * 4) * 4,
                 vT + (iy_lo * 32 + ix) * 128 + c4 * 4);
        }
        cp_commit();
        cp_wait0();
    }
    __syncthreads();

    int cur = 0;
    for (int iy = iy_lo; iy <= iy_hi; iy++) {
        if (iy < iy_hi) {
            const int nb = cur ^ 1;
            #pragma unroll
            for (int r = 0; r < 4; r++) {
                int i = tid + r * 256;
                int ix = i >> 5, c4 = i & 31;
                cp16(smb + (nb * AGG_SLABSZ + (ix + 7) * 132 + c4 * 4) * 4,
                     vT + ((iy + 1) * 32 + ix) * 128 + c4 * 4);
            }
            cp_commit();
        }
        const float* slab = sm + cur * AGG_SLABSZ;

        const int dyA = iy - y0 + 7;     // 0..15 (15 = invalid for y0)
        const int dyB = dyA - 1;         // -1..14 (-1 = invalid for y1)
        const bool vA = (dyA <= 14);
        const bool vB = (dyB >= 0);

        if (vA && vB) {
            const float* pA = Lb + (dyA * 15) * 1024 + y0 * 32 + x;
            const float* pB = Lb + (dyB * 15) * 1024 + y1 * 32 + x;
            #pragma unroll
            for (int dx = 0; dx < 15; dx++) {
                float aw0 = pA[dx << 10];
                float aw1 = pB[dx << 10];
                u64 a0 = pack2(aw0, aw0), a1 = pack2(aw1, aw1);
                const float* vp = slab + (x + dx) * 132 + cbase;
                ulonglong2 v0 = *(const ulonglong2*)(vp);
                ulonglong2 v1 = *(const ulonglong2*)(vp + 4);
                ulonglong2 v2 = *(const ulonglong2*)(vp + 8);
                ulonglong2 v3 = *(const ulonglong2*)(vp + 12);
                acc0[0] = fma2(a0, v0.x, acc0[0]); acc0[1] = fma2(a0, v0.y, acc0[1]);
                acc0[2] = fma2(a0, v1.x, acc0[2]); acc0[3] = fma2(a0, v1.y, acc0[3]);
                acc0[4] = fma2(a0, v2.x, acc0[4]); acc0[5] = fma2(a0, v2.y, acc0[5]);
                acc0[6] = fma2(a0, v3.x, acc0[6]); acc0[7] = fma2(a0, v3.y, acc0[7]);
                acc1[0] = fma2(a1, v0.x, acc1[0]); acc1[1] = fma2(a1, v0.y, acc1[1]);
                acc1[2] = fma2(a1, v1.x, acc1[2]); acc1[3] = fma2(a1, v1.y, acc1[3]);
                acc1[4] = fma2(a1, v2.x, acc1[4]); acc1[5] = fma2(a1, v2.y, acc1[5]);
                acc1[6] = fma2(a1, v3.x, acc1[6]); acc1[7] = fma2(a1, v3.y, acc1[7]);
            }
        } else if (vA) {
            const float* pA = Lb + (dyA * 15) * 1024 + y0 * 32 + x;
            #pragma unroll
            for (int dx = 0; dx < 15; dx++) {
                float aw = pA[dx << 10];
                u64 a2 = pack2(aw, aw);
                const float* vp = slab + (x + dx) * 132 + cbase;
                ulonglong2 v0 = *(const ulonglong2*)(vp);
                ulonglong2 v1 = *(const ulonglong2*)(vp + 4);
                ulonglong2 v2 = *(const ulonglong2*)(vp + 8);
                ulonglong2 v3 = *(const ulonglong2*)(vp + 12);
                acc0[0] = fma2(a2, v0.x, acc0[0]); acc0[1] = fma2(a2, v0.y, acc0[1]);
                acc0[2] = fma2(a2, v1.x, acc0[2]); acc0[3] = fma2(a2, v1.y, acc0[3]);
                acc0[4] = fma2(a2, v2.x, acc0[4]); acc0[5] = fma2(a2, v2.y, acc0[5]);
                acc0[6] = fma2(a2, v3.x, acc0[6]); acc0[7] = fma2(a2, v3.y, acc0[7]);
            }
        } else {
            const float* pB = Lb + (dyB * 15) * 1024 + y1 * 32 + x;
            #pragma unroll
            for (int dx = 0; dx < 15; dx++) {
                float aw = pB[dx << 10];
                u64 a2 = pack2(aw, aw);
                const float* vp = slab + (x + dx) * 132 + cbase;
                ulonglong2 v0 = *(const ulonglong2*)(vp);
                ulonglong2 v1 = *(const ulonglong2*)(vp + 4);
                ulonglong2 v2 = *(const ulonglong2*)(vp + 8);
                ulonglong2 v3 = *(const ulonglong2*)(vp + 12);
                acc1[0] = fma2(a2, v0.x, acc1[0]); acc1[1] = fma2(a2, v0.y, acc1[1]);
                acc1[2] = fma2(a2, v1.x, acc1[2]); acc1[3] = fma2(a2, v1.y, acc1[3]);
                acc1[4] = fma2(a2, v2.x, acc1[4]); acc1[5] = fma2(a2, v2.y, acc1[5]);
                acc1[6] = fma2(a2, v3.x, acc1[6]); acc1[7] = fma2(a2, v3.y, acc1[7]);
            }
        }

        cp_wait0();
        __syncthreads();
        cur ^= 1;
    }

    float* a0p = g_agg + ((y0 * 32 + x) * 4 + n) * 256 + g * 128 + cbase;
    float* a1p = g_agg + ((y1 * 32 + x) * 4 + n) * 256 + g * 128 + cbase;
    #pragma unroll
    for (int j = 0; j < 8; j++) {
        *(float2*)(a0p + 2 * j) = unpack2(acc0[j]);
        *(float2*)(a1p + 2 * j) = unpack2(acc1[j]);
    }
}

__global__ void __launch_bounds__(256) aggbias_kernel() {
    extern __shared__ float sm[];
    unsigned smb = (unsigned)__cvta_generic_to_shared(sm);
    const int bid = blockIdx.x;
    if (bid < 128) agg_body(sm, smb, bid);
    else           bias_body(sm, bid - 128);
}

// ---------------------------------------------------------------------------
// Output FC: out[r, d] = sum_c (agg+aggb)[r, c] * Wfc[d, c] + bfc[d]
// ---------------------------------------------------------------------------
__global__ void __launch_bounds__(256) fc_kernel(
        const float* __restrict__ Wfc, const float* __restrict__ bfc,
        float* __restrict__ out) {
    __shared__ float w_s[32 * 68];
    __shared__ float x_s[32 * 128];

    const int r0 = blockIdx.x * 64;
    const int d0 = blockIdx.y * 128;
    const int tid = threadIdx.x;
    const int td = tid >> 4;
    const int tm = tid & 15;

    u64 acc[4][4];
    #pragma unroll
    for (int mq = 0; mq < 4; mq++) {
        int d = d0 + 2 * tm + 32 * mq;
        u64 bb = pack2(bfc[d], bfc[d + 1]);
        #pragma unroll
        for (int rr = 0; rr < 4; rr++) acc[rr][mq] = bb;
    }

    const int lrq = tid >> 3;
    const int lc4 = tid & 7;
    const int ld  = tid & 127;
    const int lch = tid >> 7;

    for (int kb = 0; kb < 8; kb++) {
        const int k0 = kb * 32;
        {
            const int i1 = (r0 + lrq) * 256 + k0 + lc4 * 4;
            const int i2 = (r0 + lrq + 32) * 256 + k0 + lc4 * 4;
            float4 fa = *(const float4*)(g_agg + i1);
            float4 ba = *(const float4*)(g_aggb + i1);
            float4 fb = *(const float4*)(g_agg + i2);
            float4 bb = *(const float4*)(g_aggb + i2);
            fa.x += ba.x; fa.y += ba.y; fa.z += ba.z; fa.w += ba.w;
            fb.x += bb.x; fb.y += bb.y; fb.z += bb.z; fb.w += bb.w;
            w_s[(lc4 * 4 + 0) * 68 + lrq] = fa.x;
            w_s[(lc4 * 4 + 1) * 68 + lrq] = fa.y;
            w_s[(lc4 * 4 + 2) * 68 + lrq] = fa.z;
            w_s[(lc4 * 4 + 3) * 68 + lrq] = fa.w;
            w_s[(lc4 * 4 + 0) * 68 + lrq + 32] = fb.x;
            w_s[(lc4 * 4 + 1) * 68 + lrq + 32] = fb.y;
            w_s[(lc4 * 4 + 2) * 68 + lrq + 32] = fb.z;
            w_s[(lc4 * 4 + 3) * 68 + lrq + 32] = fb.w;
        }
        #pragma unroll
        for (int i = 0; i < 4; i++) {
            int cq = lch * 4 + i;
            float4 f = *(const float4*)(Wfc + (d0 + ld) * 256 + k0 + cq * 4);
            x_s[(cq * 4 + 0) * 128 + ld] = f.x;
            x_s[(cq * 4 + 1) * 128 + ld] = f.y;
            x_s[(cq * 4 + 2) * 128 + ld] = f.z;
            x_s[(cq * 4 + 3) * 128 + ld] = f.w;
        }
        __syncthreads();

        #pragma unroll 8
        for (int kk = 0; kk < 32; kk++) {
            float4 wv = *(const float4*)(w_s + kk * 68 + td * 4);
            u64 xv[4];
            #pragma unroll
            for (int mq = 0; mq < 4; mq++)
                xv[mq] = *(const u64*)(x_s + kk * 128 + 2 * tm + 32 * mq);
            u64 w0 = pack2(wv.x, wv.x), w1 = pack2(wv.y, wv.y);
            u64 w2 = pack2(wv.z, wv.z), w3 = pack2(wv.w, wv.w);
            #pragma unroll
            for (int mq = 0; mq < 4; mq++) {
                acc[0][mq] = fma2(w0, xv[mq], acc[0][mq]);
                acc[1][mq] = fma2(w1, xv[mq], acc[1][mq]);
                acc[2][mq] = fma2(w2, xv[mq], acc[2][mq]);
                acc[3][mq] = fma2(w3, xv[mq], acc[3][mq]);
            }
        }
        __syncthreads();
    }

    #pragma unroll
    for (int rr = 0; rr < 4; rr++) {
        float* op = out + (r0 + td * 4 + rr) * 256 + d0 + 2 * tm;
        #pragma unroll
        for (int mq = 0; mq < 4; mq++)
            *(float2*)(op + 32 * mq) = unpack2(acc[rr][mq]);
    }
}

// ---------------------------------------------------------------------------
extern "C" void kernel_launch(void* const* d_in, const int* in_sizes, int n_in,
                              void* d_out, int out_size) {
    const float* q    = (const float*)d_in[0];
    const float* k    = (const float*)d_in[1];
    const float* v    = (const float*)d_in[2];
    const float* Wq   = (const float*)d_in[3];
    const float* bq   = (const float*)d_in[4];
    const float* Wk   = (const float*)d_in[5];
    const float* bk   = (const float*)d_in[6];
    const float* Wv   = (const float*)d_in[7];
    const float* bv   = (const float*)d_in[8];
    const float* Wrel = (const float*)d_in[9];
    const float* brel = (const float*)d_in[10];
    const float* Vb   = (const float*)d_in[11];
    const float* Wfc  = (const float*)d_in[12];
    const float* bfc  = (const float*)d_in[13];
    float* out = (float*)d_out;

    cudaFuncSetAttribute(relqk_kernel, cudaFuncAttributeMaxDynamicSharedMemorySize,
                         QK_SMEM_BYTES);
    cudaFuncSetAttribute(aggbias_kernel, cudaFuncAttributeMaxDynamicSharedMemorySize,
                         AGG_BYTES);

    dim3 pg(32, 4, 4);
    proj_kernel<<<pg, 128>>>(q, k, v, Wq, bq, Wk, bk, Wv, bv, Vb);

    relqk_kernel<<<384, 256, QK_SMEM_BYTES>>>(Wrel, brel);

    dim3 sg(32, 8);
    softmax_kernel<<<sg, 256>>>();

    aggbias_kernel<<<256, 256, AGG_BYTES>>>();

    dim3 fg(64, 2);
    fc_kernel<<<fg, 256>>>(Wfc, bfc, out);
}